// round 3
// baseline (speedup 1.0000x reference)
#include <cuda_runtime.h>
#include <cstdint>
#include <cstddef>

#define D_MODEL 1024
#define NHEADS  16
#define DEPTH   64
#define BATCH   2
#define SEQ     2048
#define M_TOTAL (BATCH * SEQ)   // 4096

// Scratch (alloc-free rule: __device__ globals)
__device__ float g_Qp[(size_t)M_TOTAL * D_MODEL];      // 16 MB
__device__ float g_KV[(size_t)M_TOTAL * 2 * DEPTH];    //  2 MB
__device__ float g_attn[(size_t)M_TOTAL * D_MODEL];    // 16 MB

// ---------------------------------------------------------------------------
// C[M,N] = A[M,K] @ W[N,K]^T + bias[N]   (both operands K-contiguous, "NT")
// 64x64 tile, BK=16, 256 threads, 4x4 microtile. Smem tiles stored k-major
// [16][68] so inner-loop reads are float4 with broadcast-friendly addressing.
// ---------------------------------------------------------------------------
__global__ __launch_bounds__(256) void gemm_nt_bias(
    const float* __restrict__ A, const float* __restrict__ W,
    const float* __restrict__ bias, float* __restrict__ C,
    int M, int N, int K)
{
    __shared__ float As[16][68];
    __shared__ float Ws[16][68];
    int tid = threadIdx.x;
    int m0 = blockIdx.y * 64, n0 = blockIdx.x * 64;
    int lr = tid >> 2;        // 0..63 row within tile
    int lq = tid & 3;         // which float4 along k
    int tx = tid & 15, ty = tid >> 4;

    float acc[4][4];
#pragma unroll
    for (int i = 0; i < 4; i++)
#pragma unroll
        for (int j = 0; j < 4; j++) acc[i][j] = 0.f;

    const float* Aptr = A + (size_t)(m0 + lr) * K + lq * 4;
    const float* Wptr = W + (size_t)(n0 + lr) * K + lq * 4;

    for (int k0 = 0; k0 < K; k0 += 16) {
        float4 av = *(const float4*)(Aptr + k0);
        float4 wv = *(const float4*)(Wptr + k0);
        __syncthreads();
        As[lq * 4 + 0][lr] = av.x; As[lq * 4 + 1][lr] = av.y;
        As[lq * 4 + 2][lr] = av.z; As[lq * 4 + 3][lr] = av.w;
        Ws[lq * 4 + 0][lr] = wv.x; Ws[lq * 4 + 1][lr] = wv.y;
        Ws[lq * 4 + 2][lr] = wv.z; Ws[lq * 4 + 3][lr] = wv.w;
        __syncthreads();
#pragma unroll
        for (int kk = 0; kk < 16; kk++) {
            float4 a = *(const float4*)&As[kk][ty * 4];
            float4 w = *(const float4*)&Ws[kk][tx * 4];
            acc[0][0] += a.x * w.x; acc[0][1] += a.x * w.y; acc[0][2] += a.x * w.z; acc[0][3] += a.x * w.w;
            acc[1][0] += a.y * w.x; acc[1][1] += a.y * w.y; acc[1][2] += a.y * w.z; acc[1][3] += a.y * w.w;
            acc[2][0] += a.z * w.x; acc[2][1] += a.z * w.y; acc[2][2] += a.z * w.z; acc[2][3] += a.z * w.w;
            acc[3][0] += a.w * w.x; acc[3][1] += a.w * w.y; acc[3][2] += a.w * w.z; acc[3][3] += a.w * w.w;
        }
    }

    float4 bv = *(const float4*)&bias[n0 + tx * 4];
#pragma unroll
    for (int i = 0; i < 4; i++) {
        float4 o;
        o.x = acc[i][0] + bv.x; o.y = acc[i][1] + bv.y;
        o.z = acc[i][2] + bv.z; o.w = acc[i][3] + bv.w;
        *(float4*)&C[(size_t)(m0 + ty * 4 + i) * N + n0 + tx * 4] = o;
    }
}

// ---------------------------------------------------------------------------
// Fused attention: one block = 16 query rows of one (b,h).
// Phase 1: logits rows (16 x 2048) built in smem, K tiles staged in smem.
// Phase 2: softmax per row; normalized weights written to global (only write).
// Phase 3: PV accumulation with V tiles staged in smem.
// Smem: logits 16*2048 + tile 128*76 + qs 16*64 floats = 174080 B.
// ---------------------------------------------------------------------------
#define TQ 16
#define TK 128
#define TPAD 76
#define ATTN_SMEM_BYTES ((TQ * SEQ + TK * TPAD + TQ * DEPTH) * 4)

__global__ __launch_bounds__(256) void attn_kernel(
    const float* __restrict__ Qp, const float* __restrict__ KV,
    float* __restrict__ Wout, float* __restrict__ Aout)
{
    extern __shared__ float sm[];
    float* logits = sm;                    // TQ * SEQ
    float* tile   = sm + TQ * SEQ;         // TK * TPAD
    float* qs     = tile + TK * TPAD;      // TQ * DEPTH

    int tid = threadIdx.x;
    int b = blockIdx.z, h = blockIdx.y, q0 = blockIdx.x * TQ;

    // load q rows (16 x 64 floats, 1 float4 per thread)
    {
        int q = tid >> 4, dq = (tid & 15) * 4;
        *(float4*)&qs[q * DEPTH + dq] =
            *(const float4*)&Qp[((size_t)(b * SEQ + q0 + q)) * D_MODEL + h * DEPTH + dq];
    }

    int qh = tid >> 6;          // 0..3 -> q block of 4
    int kt = tid & 63;          // k, also k+64
    int wid = tid >> 5, lane = tid & 31;

    // ---- Phase 1: logits ----
    for (int kc = 0; kc < SEQ; kc += TK) {
        __syncthreads();
#pragma unroll
        for (int i = 0; i < 8; i++) {
            int e = tid + i * 256;              // 2048 float4 units
            int k = e >> 4, dq = (e & 15) * 4;
            *(float4*)&tile[k * TPAD + dq] =
                *(const float4*)&KV[((size_t)(b * SEQ + kc + k)) * (2 * DEPTH) + dq];
        }
        __syncthreads();

        float acc[4][2];
#pragma unroll
        for (int i = 0; i < 4; i++) { acc[i][0] = 0.f; acc[i][1] = 0.f; }

#pragma unroll
        for (int d4 = 0; d4 < DEPTH; d4 += 4) {
            float4 k0 = *(const float4*)&tile[kt * TPAD + d4];
            float4 k1 = *(const float4*)&tile[(kt + 64) * TPAD + d4];
#pragma unroll
            for (int i = 0; i < 4; i++) {
                float4 qv = *(const float4*)&qs[(qh * 4 + i) * DEPTH + d4];
                acc[i][0] += qv.x * k0.x + qv.y * k0.y + qv.z * k0.z + qv.w * k0.w;
                acc[i][1] += qv.x * k1.x + qv.y * k1.y + qv.z * k1.z + qv.w * k1.w;
            }
        }
#pragma unroll
        for (int i = 0; i < 4; i++) {
            logits[(qh * 4 + i) * SEQ + kc + kt]      = acc[i][0] * 0.125f;
            logits[(qh * 4 + i) * SEQ + kc + kt + 64] = acc[i][1] * 0.125f;
        }
    }
    __syncthreads();

    // ---- Phase 2: softmax (warp w handles rows w and w+8) ----
#pragma unroll
    for (int r = 0; r < 2; r++) {
        int q = wid + 8 * r;
        float* row = logits + q * SEQ;
        float m = -1e30f;
        for (int k = lane; k < SEQ; k += 32) m = fmaxf(m, row[k]);
#pragma unroll
        for (int o = 16; o; o >>= 1) m = fmaxf(m, __shfl_xor_sync(0xffffffffu, m, o));
        float s = 0.f;
        for (int k = lane; k < SEQ; k += 32) {
            float e = __expf(row[k] - m);
            row[k] = e;
            s += e;
        }
#pragma unroll
        for (int o = 16; o; o >>= 1) s += __shfl_xor_sync(0xffffffffu, s, o);
        float inv = 1.f / s;
        float* wrow = Wout + (((size_t)(b * NHEADS + h)) * SEQ + (q0 + q)) * SEQ;
        for (int k = lane; k < SEQ; k += 32) {
            float p = row[k] * inv;
            row[k] = p;
            wrow[k] = p;
        }
    }

    // ---- Phase 3: PV (warp w owns rows w, w+8; lane owns d0=2*lane, d0+1) ----
    float a00 = 0.f, a01 = 0.f, a10 = 0.f, a11 = 0.f;
    int d0 = lane * 2;
    for (int kc = 0; kc < SEQ; kc += TK) {
        __syncthreads();
#pragma unroll
        for (int i = 0; i < 8; i++) {
            int e = tid + i * 256;
            int k = e >> 4, dq = (e & 15) * 4;
            *(float4*)&tile[k * TPAD + dq] =
                *(const float4*)&KV[((size_t)(b * SEQ + kc + k)) * (2 * DEPTH) + DEPTH + dq];
        }
        __syncthreads();
#pragma unroll 4
        for (int k = 0; k < TK; k++) {
            float2 v = *(const float2*)&tile[k * TPAD + d0];
            float w0 = logits[wid * SEQ + kc + k];
            float w1 = logits[(wid + 8) * SEQ + kc + k];
            a00 += w0 * v.x; a01 += w0 * v.y;
            a10 += w1 * v.x; a11 += w1 * v.y;
        }
    }
    size_t base0 = ((size_t)(b * SEQ + q0 + wid)) * D_MODEL + h * DEPTH + d0;
    size_t base1 = ((size_t)(b * SEQ + q0 + wid + 8)) * D_MODEL + h * DEPTH + d0;
    Aout[base0] = a00; Aout[base0 + 1] = a01;
    Aout[base1] = a10; Aout[base1 + 1] = a11;
}

// ---------------------------------------------------------------------------
extern "C" void kernel_launch(void* const* d_in, const int* in_sizes, int n_in,
                              void* d_out, int out_size)
{
    const float* Q       = (const float*)d_in[0];
    const float* K       = (const float*)d_in[1];
    // d_in[2] = V  (unused by reference: V comes from the KV projection)
    const float* WQ_w    = (const float*)d_in[3];
    const float* WQ_b    = (const float*)d_in[4];
    const float* WKV_w   = (const float*)d_in[5];
    const float* WKV_b   = (const float*)d_in[6];
    const float* dense_w = (const float*)d_in[7];
    const float* dense_b = (const float*)d_in[8];

    float* out     = (float*)d_out;                           // [2,2048,1024]
    float* weights = out + (size_t)M_TOTAL * D_MODEL;         // [2,16,2048,2048]

    float *qp, *kv, *attn;
    cudaGetSymbolAddress((void**)&qp,   g_Qp);
    cudaGetSymbolAddress((void**)&kv,   g_KV);
    cudaGetSymbolAddress((void**)&attn, g_attn);

    cudaFuncSetAttribute(attn_kernel,
                         cudaFuncAttributeMaxDynamicSharedMemorySize,
                         ATTN_SMEM_BYTES);

    // 1) Qp = Q @ WQ_w^T + b        [4096,1024]
    gemm_nt_bias<<<dim3(D_MODEL / 64, M_TOTAL / 64), 256>>>(
        Q, WQ_w, WQ_b, qp, M_TOTAL, D_MODEL, D_MODEL);

    // 2) KV = K @ WKV_w^T + b       [4096,128]
    gemm_nt_bias<<<dim3((2 * DEPTH) / 64, M_TOTAL / 64), 256>>>(
        K, WKV_w, WKV_b, kv, M_TOTAL, 2 * DEPTH, D_MODEL);

    // 3) attention: weights (global out) + attn context (scratch)
    attn_kernel<<<dim3(SEQ / TQ, NHEADS, BATCH), 256, ATTN_SMEM_BYTES>>>(
        qp, kv, weights, attn);

    // 4) out = attn @ dense_w^T + b [4096,1024]
    gemm_nt_bias<<<dim3(D_MODEL / 64, M_TOTAL / 64), 256>>>(
        attn, dense_w, dense_b, out, M_TOTAL, D_MODEL, D_MODEL);
}

// round 4
// speedup vs baseline: 1.0002x; 1.0002x over previous
#include <cuda_runtime.h>
#include <cstdint>
#include <cstddef>

#define D_MODEL 1024
#define NHEADS  16
#define DEPTH   64
#define BATCH   2
#define SEQ     2048
#define M_TOTAL (BATCH * SEQ)   // 4096

// Scratch (alloc-free rule: __device__ globals)
__device__ float g_Qp[(size_t)M_TOTAL * D_MODEL];      // 16 MB
__device__ float g_KV[(size_t)M_TOTAL * 2 * DEPTH];    //  2 MB
__device__ float g_attn[(size_t)M_TOTAL * D_MODEL];    // 16 MB

// ---------------------------------------------------------------------------
// C[M,N] = A[M,K] @ W[N,K]^T + bias[N]   (both operands K-contiguous, "NT")
// 64x64 tile, BK=16, 256 threads, 4x4 microtile. Smem tiles stored k-major
// [16][68] so inner-loop reads are float4 with broadcast-friendly addressing.
// ---------------------------------------------------------------------------
__global__ __launch_bounds__(256) void gemm_nt_bias(
    const float* __restrict__ A, const float* __restrict__ W,
    const float* __restrict__ bias, float* __restrict__ C,
    int M, int N, int K)
{
    __shared__ float As[16][68];
    __shared__ float Ws[16][68];
    int tid = threadIdx.x;
    int m0 = blockIdx.y * 64, n0 = blockIdx.x * 64;
    int lr = tid >> 2;        // 0..63 row within tile
    int lq = tid & 3;         // which float4 along k
    int tx = tid & 15, ty = tid >> 4;

    float acc[4][4];
#pragma unroll
    for (int i = 0; i < 4; i++)
#pragma unroll
        for (int j = 0; j < 4; j++) acc[i][j] = 0.f;

    const float* Aptr = A + (size_t)(m0 + lr) * K + lq * 4;
    const float* Wptr = W + (size_t)(n0 + lr) * K + lq * 4;

    for (int k0 = 0; k0 < K; k0 += 16) {
        float4 av = *(const float4*)(Aptr + k0);
        float4 wv = *(const float4*)(Wptr + k0);
        __syncthreads();
        As[lq * 4 + 0][lr] = av.x; As[lq * 4 + 1][lr] = av.y;
        As[lq * 4 + 2][lr] = av.z; As[lq * 4 + 3][lr] = av.w;
        Ws[lq * 4 + 0][lr] = wv.x; Ws[lq * 4 + 1][lr] = wv.y;
        Ws[lq * 4 + 2][lr] = wv.z; Ws[lq * 4 + 3][lr] = wv.w;
        __syncthreads();
#pragma unroll
        for (int kk = 0; kk < 16; kk++) {
            float4 a = *(const float4*)&As[kk][ty * 4];
            float4 w = *(const float4*)&Ws[kk][tx * 4];
            acc[0][0] += a.x * w.x; acc[0][1] += a.x * w.y; acc[0][2] += a.x * w.z; acc[0][3] += a.x * w.w;
            acc[1][0] += a.y * w.x; acc[1][1] += a.y * w.y; acc[1][2] += a.y * w.z; acc[1][3] += a.y * w.w;
            acc[2][0] += a.z * w.x; acc[2][1] += a.z * w.y; acc[2][2] += a.z * w.z; acc[2][3] += a.z * w.w;
            acc[3][0] += a.w * w.x; acc[3][1] += a.w * w.y; acc[3][2] += a.w * w.z; acc[3][3] += a.w * w.w;
        }
    }

    float4 bv = *(const float4*)&bias[n0 + tx * 4];
#pragma unroll
    for (int i = 0; i < 4; i++) {
        float4 o;
        o.x = acc[i][0] + bv.x; o.y = acc[i][1] + bv.y;
        o.z = acc[i][2] + bv.z; o.w = acc[i][3] + bv.w;
        *(float4*)&C[(size_t)(m0 + ty * 4 + i) * N + n0 + tx * 4] = o;
    }
}

// ---------------------------------------------------------------------------
// Fused attention: one block = 16 query rows of one (b,h).
// Phase 1: logits rows (16 x 2048) built in smem, K tiles staged in smem.
// Phase 2: softmax per row; normalized weights written to global (only write).
// Phase 3: PV accumulation with V tiles staged in smem.
// Smem: logits 16*2048 + tile 128*76 + qs 16*64 floats = 174080 B.
// ---------------------------------------------------------------------------
#define TQ 16
#define TK 128
#define TPAD 76
#define ATTN_SMEM_BYTES ((TQ * SEQ + TK * TPAD + TQ * DEPTH) * 4)

__global__ __launch_bounds__(256) void attn_kernel(
    const float* __restrict__ Qp, const float* __restrict__ KV,
    float* __restrict__ Wout, float* __restrict__ Aout)
{
    extern __shared__ float sm[];
    float* logits = sm;                    // TQ * SEQ
    float* tile   = sm + TQ * SEQ;         // TK * TPAD
    float* qs     = tile + TK * TPAD;      // TQ * DEPTH

    int tid = threadIdx.x;
    int b = blockIdx.z, h = blockIdx.y, q0 = blockIdx.x * TQ;

    // load q rows (16 x 64 floats, 1 float4 per thread)
    {
        int q = tid >> 4, dq = (tid & 15) * 4;
        *(float4*)&qs[q * DEPTH + dq] =
            *(const float4*)&Qp[((size_t)(b * SEQ + q0 + q)) * D_MODEL + h * DEPTH + dq];
    }

    int qh = tid >> 6;          // 0..3 -> q block of 4
    int kt = tid & 63;          // k, also k+64
    int wid = tid >> 5, lane = tid & 31;

    // ---- Phase 1: logits ----
    for (int kc = 0; kc < SEQ; kc += TK) {
        __syncthreads();
#pragma unroll
        for (int i = 0; i < 8; i++) {
            int e = tid + i * 256;              // 2048 float4 units
            int k = e >> 4, dq = (e & 15) * 4;
            *(float4*)&tile[k * TPAD + dq] =
                *(const float4*)&KV[((size_t)(b * SEQ + kc + k)) * (2 * DEPTH) + dq];
        }
        __syncthreads();

        float acc[4][2];
#pragma unroll
        for (int i = 0; i < 4; i++) { acc[i][0] = 0.f; acc[i][1] = 0.f; }

#pragma unroll
        for (int d4 = 0; d4 < DEPTH; d4 += 4) {
            float4 k0 = *(const float4*)&tile[kt * TPAD + d4];
            float4 k1 = *(const float4*)&tile[(kt + 64) * TPAD + d4];
#pragma unroll
            for (int i = 0; i < 4; i++) {
                float4 qv = *(const float4*)&qs[(qh * 4 + i) * DEPTH + d4];
                acc[i][0] += qv.x * k0.x + qv.y * k0.y + qv.z * k0.z + qv.w * k0.w;
                acc[i][1] += qv.x * k1.x + qv.y * k1.y + qv.z * k1.z + qv.w * k1.w;
            }
        }
#pragma unroll
        for (int i = 0; i < 4; i++) {
            logits[(qh * 4 + i) * SEQ + kc + kt]      = acc[i][0] * 0.125f;
            logits[(qh * 4 + i) * SEQ + kc + kt + 64] = acc[i][1] * 0.125f;
        }
    }
    __syncthreads();

    // ---- Phase 2: softmax (warp w handles rows w and w+8) ----
#pragma unroll
    for (int r = 0; r < 2; r++) {
        int q = wid + 8 * r;
        float* row = logits + q * SEQ;
        float m = -1e30f;
        for (int k = lane; k < SEQ; k += 32) m = fmaxf(m, row[k]);
#pragma unroll
        for (int o = 16; o; o >>= 1) m = fmaxf(m, __shfl_xor_sync(0xffffffffu, m, o));
        float s = 0.f;
        for (int k = lane; k < SEQ; k += 32) {
            float e = __expf(row[k] - m);
            row[k] = e;
            s += e;
        }
#pragma unroll
        for (int o = 16; o; o >>= 1) s += __shfl_xor_sync(0xffffffffu, s, o);
        float inv = 1.f / s;
        float* wrow = Wout + (((size_t)(b * NHEADS + h)) * SEQ + (q0 + q)) * SEQ;
        for (int k = lane; k < SEQ; k += 32) {
            float p = row[k] * inv;
            row[k] = p;
            wrow[k] = p;
        }
    }

    // ---- Phase 3: PV (warp w owns rows w, w+8; lane owns d0=2*lane, d0+1) ----
    float a00 = 0.f, a01 = 0.f, a10 = 0.f, a11 = 0.f;
    int d0 = lane * 2;
    for (int kc = 0; kc < SEQ; kc += TK) {
        __syncthreads();
#pragma unroll
        for (int i = 0; i < 8; i++) {
            int e = tid + i * 256;
            int k = e >> 4, dq = (e & 15) * 4;
            *(float4*)&tile[k * TPAD + dq] =
                *(const float4*)&KV[((size_t)(b * SEQ + kc + k)) * (2 * DEPTH) + DEPTH + dq];
        }
        __syncthreads();
#pragma unroll 4
        for (int k = 0; k < TK; k++) {
            float2 v = *(const float2*)&tile[k * TPAD + d0];
            float w0 = logits[wid * SEQ + kc + k];
            float w1 = logits[(wid + 8) * SEQ + kc + k];
            a00 += w0 * v.x; a01 += w0 * v.y;
            a10 += w1 * v.x; a11 += w1 * v.y;
        }
    }
    size_t base0 = ((size_t)(b * SEQ + q0 + wid)) * D_MODEL + h * DEPTH + d0;
    size_t base1 = ((size_t)(b * SEQ + q0 + wid + 8)) * D_MODEL + h * DEPTH + d0;
    Aout[base0] = a00; Aout[base0 + 1] = a01;
    Aout[base1] = a10; Aout[base1 + 1] = a11;
}

// ---------------------------------------------------------------------------
extern "C" void kernel_launch(void* const* d_in, const int* in_sizes, int n_in,
                              void* d_out, int out_size)
{
    const float* Q       = (const float*)d_in[0];
    const float* K       = (const float*)d_in[1];
    // d_in[2] = V  (unused by reference: V comes from the KV projection)
    const float* WQ_w    = (const float*)d_in[3];
    const float* WQ_b    = (const float*)d_in[4];
    const float* WKV_w   = (const float*)d_in[5];
    const float* WKV_b   = (const float*)d_in[6];
    const float* dense_w = (const float*)d_in[7];
    const float* dense_b = (const float*)d_in[8];

    float* out     = (float*)d_out;                           // [2,2048,1024]
    float* weights = out + (size_t)M_TOTAL * D_MODEL;         // [2,16,2048,2048]

    float *qp, *kv, *attn;
    cudaGetSymbolAddress((void**)&qp,   g_Qp);
    cudaGetSymbolAddress((void**)&kv,   g_KV);
    cudaGetSymbolAddress((void**)&attn, g_attn);

    cudaFuncSetAttribute(attn_kernel,
                         cudaFuncAttributeMaxDynamicSharedMemorySize,
                         ATTN_SMEM_BYTES);

    // 1) Qp = Q @ WQ_w^T + b        [4096,1024]
    gemm_nt_bias<<<dim3(D_MODEL / 64, M_TOTAL / 64), 256>>>(
        Q, WQ_w, WQ_b, qp, M_TOTAL, D_MODEL, D_MODEL);

    // 2) KV = K @ WKV_w^T + b       [4096,128]
    gemm_nt_bias<<<dim3((2 * DEPTH) / 64, M_TOTAL / 64), 256>>>(
        K, WKV_w, WKV_b, kv, M_TOTAL, 2 * DEPTH, D_MODEL);

    // 3) attention: weights (global out) + attn context (scratch)
    attn_kernel<<<dim3(SEQ / TQ, NHEADS, BATCH), 256, ATTN_SMEM_BYTES>>>(
        qp, kv, weights, attn);

    // 4) out = attn @ dense_w^T + b [4096,1024]
    gemm_nt_bias<<<dim3(D_MODEL / 64, M_TOTAL / 64), 256>>>(
        attn, dense_w, dense_b, out, M_TOTAL, D_MODEL, D_MODEL);
}

// round 6
// speedup vs baseline: 1.4933x; 1.4930x over previous
#include <cuda_runtime.h>
#include <cstdint>
#include <cstddef>

#define D_MODEL 1024
#define NHEADS  16
#define DEPTH   64
#define BATCH   2
#define SEQ     2048
#define M_TOTAL (BATCH * SEQ)

__device__ float g_Qp[(size_t)M_TOTAL * D_MODEL];
__device__ float g_KV[(size_t)M_TOTAL * 2 * DEPTH];
__device__ float g_attn[(size_t)M_TOTAL * D_MODEL];

// ---------------------------------------------------------------------------
// helpers (all baseline PTX: sm_80-level, legal on compute_103)
// ---------------------------------------------------------------------------
__device__ __forceinline__ uint32_t smem_u32(const void* p) {
    uint32_t a;
    asm("{ .reg .u64 t; cvta.to.shared.u64 t, %1; cvt.u32.u64 %0, t; }" : "=r"(a) : "l"(p));
    return a;
}
__device__ __forceinline__ uint32_t pack_bf16(float lo, float hi) {
    uint32_t r;
    asm("cvt.rn.bf16x2.f32 %0, %1, %2;" : "=r"(r) : "f"(hi), "f"(lo));
    return r;
}
__device__ __forceinline__ void mma_bf16(float* c, const uint32_t* a, const uint32_t* b) {
    asm volatile("mma.sync.aligned.m16n8k16.row.col.f32.bf16.bf16.f32 "
        "{%0,%1,%2,%3}, {%4,%5,%6,%7}, {%8,%9}, {%0,%1,%2,%3};"
        : "+f"(c[0]), "+f"(c[1]), "+f"(c[2]), "+f"(c[3])
        : "r"(a[0]), "r"(a[1]), "r"(a[2]), "r"(a[3]), "r"(b[0]), "r"(b[1]));
}
#define LDSM_X4(r0, r1, r2, r3, addr) \
    asm volatile("ldmatrix.sync.aligned.m8n8.x4.shared.b16 {%0,%1,%2,%3}, [%4];" \
        : "=r"(r0), "=r"(r1), "=r"(r2), "=r"(r3) : "r"(addr))
#define LDSM_X2T(r0, r1, addr) \
    asm volatile("ldmatrix.sync.aligned.m8n8.x2.trans.shared.b16 {%0,%1}, [%2];" \
        : "=r"(r0), "=r"(r1) : "r"(addr))

// ---------------------------------------------------------------------------
// attn smem layout (bytes). All strides chosen for conflict-free frag loads.
//   logits : 16 rows x 2052 f32  (pad 4)
//   K/V    : 128 rows x 72 bf16 hi + mid  (pad 8 -> (4g+t) banks distinct)
//   Q      : 16 rows x 72 bf16 hi + mid
//   P      : 16 rows x 264 bf16 hi + mid (pad 8 -> ldmatrix conflict-free)
// ---------------------------------------------------------------------------
#define LSTRIDE 2052
#define KSTRIDE 36          // words per K/V row (72 bf16)
#define PSTRIDE 132         // words per P row (264 bf16)
#define OFF_LOG  0
#define OFF_KHI  (16 * LSTRIDE * 4)                 // 131328
#define OFF_KMID (OFF_KHI  + 128 * KSTRIDE * 4)     // 149760
#define OFF_QHI  (OFF_KMID + 128 * KSTRIDE * 4)     // 168192
#define OFF_QMID (OFF_QHI  + 16 * KSTRIDE * 4)      // 170496
#define OFF_PHI  (OFF_QMID + 16 * KSTRIDE * 4)      // 172800
#define OFF_PMID (OFF_PHI  + 16 * PSTRIDE * 4)      // 181248
#define ATTN_SMEM (OFF_PMID + 16 * PSTRIDE * 4)     // 189696

// split one float4 into bf16 hi (truncate) + mid (rn of residual), store 2+2 words
__device__ __forceinline__ void split_store(uint32_t* whi, uint32_t* wmid, int wi, float4 v) {
    uint32_t b0 = __float_as_uint(v.x), b1 = __float_as_uint(v.y);
    uint32_t b2 = __float_as_uint(v.z), b3 = __float_as_uint(v.w);
    uint32_t h0 = __byte_perm(b0, b1, 0x7632);
    uint32_t h1 = __byte_perm(b2, b3, 0x7632);
    float m0 = v.x - __uint_as_float(b0 & 0xFFFF0000u);
    float m1 = v.y - __uint_as_float(b1 & 0xFFFF0000u);
    float m2 = v.z - __uint_as_float(b2 & 0xFFFF0000u);
    float m3 = v.w - __uint_as_float(b3 & 0xFFFF0000u);
    *(uint2*)(whi + wi)  = make_uint2(h0, h1);
    *(uint2*)(wmid + wi) = make_uint2(pack_bf16(m0, m1), pack_bf16(m2, m3));
}

// stage 128 KV rows (doff=0 -> K, doff=64 -> V) into hi/mid [128][KSTRIDE]
__device__ __forceinline__ void stage_kv128(const float* kvb, int kc, int doff,
                                            uint32_t* whi, uint32_t* wmid, int tid) {
#pragma unroll
    for (int i = 0; i < 8; i++) {
        int e = tid + i * 256;
        int r = e >> 4, c4 = (e & 15) * 4;
        float4 v = *(const float4*)(kvb + (size_t)(kc + r) * 128 + doff + c4);
        split_store(whi, wmid, r * KSTRIDE + c4 / 2, v);
    }
}

// ===========================================================================
// Attention via mma.sync bf16x3. CTA = 16 q rows of one (b,h), 256 threads.
// ===========================================================================
__global__ __launch_bounds__(256, 1) void attn_mma(
    const float* __restrict__ Qp, const float* __restrict__ KV,
    float* __restrict__ Wout, float* __restrict__ Aout)
{
    extern __shared__ char sm[];
    const int tid = threadIdx.x, wid = tid >> 5, lane = tid & 31;
    const int gid = lane >> 2, tig = lane & 3;
    const int b = blockIdx.z, h = blockIdx.y, q0 = blockIdx.x * 16;
    const uint32_t sb = smem_u32(sm);

    float*    logits = (float*)(sm + OFF_LOG);
    uint32_t* kw_hi  = (uint32_t*)(sm + OFF_KHI);
    uint32_t* kw_mid = (uint32_t*)(sm + OFF_KMID);
    uint32_t* qw_hi  = (uint32_t*)(sm + OFF_QHI);
    uint32_t* qw_mid = (uint32_t*)(sm + OFF_QMID);
    uint32_t* pw_hi  = (uint32_t*)(sm + OFF_PHI);
    uint32_t* pw_mid = (uint32_t*)(sm + OFF_PMID);
    const float* kvb = KV + (size_t)b * SEQ * 128;

    // ---- stage Q (x0.125, exact) ----
    {
        int r = tid >> 4, c4 = (tid & 15) * 4;
        float4 v = *(const float4*)(Qp + (size_t)(b * SEQ + q0 + r) * D_MODEL + h * DEPTH + c4);
        v.x *= 0.125f; v.y *= 0.125f; v.z *= 0.125f; v.w *= 0.125f;
        split_store(qw_hi, qw_mid, r * KSTRIDE + c4 / 2, v);
    }
    __syncthreads();

    // persistent Q fragments: 4 d-steps x (a0..a3), hi & mid
    uint32_t qh[4][4], qm[4][4];
#pragma unroll
    for (int ds = 0; ds < 4; ds++) {
        int w0 = gid * KSTRIDE + ds * 8 + tig;
        int w1 = (gid + 8) * KSTRIDE + ds * 8 + tig;
        qh[ds][0] = qw_hi[w0];  qh[ds][1] = qw_hi[w1];
        qh[ds][2] = qw_hi[w0 + 4]; qh[ds][3] = qw_hi[w1 + 4];
        qm[ds][0] = qw_mid[w0]; qm[ds][1] = qw_mid[w1];
        qm[ds][2] = qw_mid[w0 + 4]; qm[ds][3] = qw_mid[w1 + 4];
    }

    // ---- Phase 1: logits = (Q*0.125) K^T, raw fp32 into smem ----
    for (int kc = 0; kc < SEQ; kc += 128) {
        __syncthreads();
        stage_kv128(kvb, kc, 0, kw_hi, kw_mid, tid);
        __syncthreads();
#pragma unroll
        for (int t2 = 0; t2 < 2; t2++) {
            int krow0 = wid * 16 + t2 * 8;          // within chunk
            float c[4] = {0.f, 0.f, 0.f, 0.f};
#pragma unroll
            for (int ds = 0; ds < 4; ds++) {
                int wi = (krow0 + gid) * KSTRIDE + ds * 8 + tig;
                uint32_t bh[2] = { kw_hi[wi],  kw_hi[wi + 4]  };
                uint32_t bm[2] = { kw_mid[wi], kw_mid[wi + 4] };
                mma_bf16(c, qh[ds], bh);   // hi*hi
                mma_bf16(c, qm[ds], bh);   // mid*hi
                mma_bf16(c, qh[ds], bm);   // hi*mid
            }
            int col = kc + krow0 + tig * 2;
            *(float2*)&logits[gid * LSTRIDE + col]       = make_float2(c[0], c[1]);
            *(float2*)&logits[(gid + 8) * LSTRIDE + col] = make_float2(c[2], c[3]);
        }
    }
    __syncthreads();

    // ---- Phase 2: softmax in-place + weights to global ----
#pragma unroll
    for (int r = 0; r < 2; r++) {
        int q = wid + 8 * r;
        float* row = logits + q * LSTRIDE;
        float m = -1e30f;
        for (int k = lane; k < SEQ; k += 32) m = fmaxf(m, row[k]);
#pragma unroll
        for (int o = 16; o; o >>= 1) m = fmaxf(m, __shfl_xor_sync(0xffffffffu, m, o));
        float s = 0.f;
        for (int k = lane; k < SEQ; k += 32) {
            float e = __expf(row[k] - m);
            row[k] = e;
            s += e;
        }
#pragma unroll
        for (int o = 16; o; o >>= 1) s += __shfl_xor_sync(0xffffffffu, s, o);
        float inv = 1.f / s;
        float* wrow = Wout + (((size_t)(b * NHEADS + h)) * SEQ + (q0 + q)) * SEQ;
        for (int k = lane; k < SEQ; k += 32) {
            float p = row[k] * inv;
            row[k] = p;
            wrow[k] = p;
        }
    }

    // ---- Phase 3: attn = P V via mma (P bf16x2-split, V ldmatrix.trans) ----
    const uint32_t pA  = sb + OFF_PHI +
        (uint32_t)(((lane & 7) + 8 * ((lane >> 3) & 1)) * (PSTRIDE * 4)) + ((lane >> 4) * 16);
    const uint32_t pAm = pA + (OFF_PMID - OFF_PHI);
    const uint32_t vR  = sb + OFF_KHI + (uint32_t)((lane & 15) * (KSTRIDE * 4)) + (uint32_t)(wid * 16);
    const uint32_t vRm = vR + (OFF_KMID - OFF_KHI);

    float acc[4] = {0.f, 0.f, 0.f, 0.f};

    for (int kc = 0; kc < SEQ; kc += 128) {
        __syncthreads();                       // prior mma reads done; logits final
        stage_kv128(kvb, kc, 64, kw_hi, kw_mid, tid);   // V chunk into K buffers
        {   // convert P chunk [16][128] -> bf16 hi/mid
            int q = tid >> 4, c0 = (tid & 15) * 8;
            const float* lp = &logits[q * LSTRIDE + kc + c0];
            float4 v0 = *(const float4*)lp;
            float4 v1 = *(const float4*)(lp + 4);
            uint32_t b0 = __float_as_uint(v0.x), b1 = __float_as_uint(v0.y);
            uint32_t b2 = __float_as_uint(v0.z), b3 = __float_as_uint(v0.w);
            uint32_t b4 = __float_as_uint(v1.x), b5 = __float_as_uint(v1.y);
            uint32_t b6 = __float_as_uint(v1.z), b7 = __float_as_uint(v1.w);
            int wi = q * PSTRIDE + c0 / 2;
            *(uint4*)(pw_hi + wi) = make_uint4(
                __byte_perm(b0, b1, 0x7632), __byte_perm(b2, b3, 0x7632),
                __byte_perm(b4, b5, 0x7632), __byte_perm(b6, b7, 0x7632));
            float m0 = v0.x - __uint_as_float(b0 & 0xFFFF0000u);
            float m1 = v0.y - __uint_as_float(b1 & 0xFFFF0000u);
            float m2 = v0.z - __uint_as_float(b2 & 0xFFFF0000u);
            float m3 = v0.w - __uint_as_float(b3 & 0xFFFF0000u);
            float m4 = v1.x - __uint_as_float(b4 & 0xFFFF0000u);
            float m5 = v1.y - __uint_as_float(b5 & 0xFFFF0000u);
            float m6 = v1.z - __uint_as_float(b6 & 0xFFFF0000u);
            float m7 = v1.w - __uint_as_float(b7 & 0xFFFF0000u);
            *(uint4*)(pw_mid + wi) = make_uint4(
                pack_bf16(m0, m1), pack_bf16(m2, m3),
                pack_bf16(m4, m5), pack_bf16(m6, m7));
        }
        __syncthreads();
#pragma unroll
        for (int ks = 0; ks < 8; ks++) {
            uint32_t ah[4], am[4], bh[2], bm[2];
            LDSM_X4(ah[0], ah[1], ah[2], ah[3], pA + ks * 32);
            LDSM_X4(am[0], am[1], am[2], am[3], pAm + ks * 32);
            LDSM_X2T(bh[0], bh[1], vR + ks * 16 * (KSTRIDE * 4));
            LDSM_X2T(bm[0], bm[1], vRm + ks * 16 * (KSTRIDE * 4));
            mma_bf16(acc, ah, bh);   // hi*hi
            mma_bf16(acc, am, bh);   // mid*hi
            mma_bf16(acc, ah, bm);   // hi*mid
        }
    }

    // store attn context: warp wid owns d-cols [wid*8, wid*8+8)
    {
        int dcol = h * DEPTH + wid * 8 + tig * 2;
        float* a0p = Aout + (size_t)(b * SEQ + q0 + gid)     * D_MODEL + dcol;
        float* a1p = Aout + (size_t)(b * SEQ + q0 + gid + 8) * D_MODEL + dcol;
        *(float2*)a0p = make_float2(acc[0], acc[1]);
        *(float2*)a1p = make_float2(acc[2], acc[3]);
    }
}

// --------------------- fp32 GEMM (unchanged, R2) ---------------------------
__global__ __launch_bounds__(256) void gemm_nt_bias(
    const float* __restrict__ A, const float* __restrict__ W,
    const float* __restrict__ bias, float* __restrict__ C,
    int M, int N, int K)
{
    __shared__ float As[16][68];
    __shared__ float Ws[16][68];
    int tid = threadIdx.x;
    int m0 = blockIdx.y * 64, n0 = blockIdx.x * 64;
    int lr = tid >> 2, lq = tid & 3;
    int tx = tid & 15, ty = tid >> 4;
    float acc[4][4];
#pragma unroll
    for (int i = 0; i < 4; i++)
#pragma unroll
        for (int j = 0; j < 4; j++) acc[i][j] = 0.f;
    const float* Aptr = A + (size_t)(m0 + lr) * K + lq * 4;
    const float* Wptr = W + (size_t)(n0 + lr) * K + lq * 4;
    for (int k0 = 0; k0 < K; k0 += 16) {
        float4 av = *(const float4*)(Aptr + k0);
        float4 wv = *(const float4*)(Wptr + k0);
        __syncthreads();
        As[lq*4+0][lr] = av.x; As[lq*4+1][lr] = av.y; As[lq*4+2][lr] = av.z; As[lq*4+3][lr] = av.w;
        Ws[lq*4+0][lr] = wv.x; Ws[lq*4+1][lr] = wv.y; Ws[lq*4+2][lr] = wv.z; Ws[lq*4+3][lr] = wv.w;
        __syncthreads();
#pragma unroll
        for (int kk = 0; kk < 16; kk++) {
            float4 a = *(const float4*)&As[kk][ty * 4];
            float4 w = *(const float4*)&Ws[kk][tx * 4];
            acc[0][0] += a.x*w.x; acc[0][1] += a.x*w.y; acc[0][2] += a.x*w.z; acc[0][3] += a.x*w.w;
            acc[1][0] += a.y*w.x; acc[1][1] += a.y*w.y; acc[1][2] += a.y*w.z; acc[1][3] += a.y*w.w;
            acc[2][0] += a.z*w.x; acc[2][1] += a.z*w.y; acc[2][2] += a.z*w.z; acc[2][3] += a.z*w.w;
            acc[3][0] += a.w*w.x; acc[3][1] += a.w*w.y; acc[3][2] += a.w*w.z; acc[3][3] += a.w*w.w;
        }
    }
    float4 bv = *(const float4*)&bias[n0 + tx * 4];
#pragma unroll
    for (int i = 0; i < 4; i++) {
        float4 o;
        o.x = acc[i][0] + bv.x; o.y = acc[i][1] + bv.y;
        o.z = acc[i][2] + bv.z; o.w = acc[i][3] + bv.w;
        *(float4*)&C[(size_t)(m0 + ty * 4 + i) * N + n0 + tx * 4] = o;
    }
}

// ---------------------------------------------------------------------------
extern "C" void kernel_launch(void* const* d_in, const int* in_sizes, int n_in,
                              void* d_out, int out_size)
{
    const float* Q       = (const float*)d_in[0];
    const float* K       = (const float*)d_in[1];
    // d_in[2] = V (unused: reference derives V from the KV projection)
    const float* WQ_w    = (const float*)d_in[3];
    const float* WQ_b    = (const float*)d_in[4];
    const float* WKV_w   = (const float*)d_in[5];
    const float* WKV_b   = (const float*)d_in[6];
    const float* dense_w = (const float*)d_in[7];
    const float* dense_b = (const float*)d_in[8];

    float* out     = (float*)d_out;
    float* weights = out + (size_t)M_TOTAL * D_MODEL;

    float *qp, *kv, *attn;
    cudaGetSymbolAddress((void**)&qp,   g_Qp);
    cudaGetSymbolAddress((void**)&kv,   g_KV);
    cudaGetSymbolAddress((void**)&attn, g_attn);

    cudaFuncSetAttribute(attn_mma, cudaFuncAttributeMaxDynamicSharedMemorySize, ATTN_SMEM);

    gemm_nt_bias<<<dim3(D_MODEL / 64, M_TOTAL / 64), 256>>>(
        Q, WQ_w, WQ_b, qp, M_TOTAL, D_MODEL, D_MODEL);
    gemm_nt_bias<<<dim3((2 * DEPTH) / 64, M_TOTAL / 64), 256>>>(
        K, WKV_w, WKV_b, kv, M_TOTAL, 2 * DEPTH, D_MODEL);
    attn_mma<<<dim3(SEQ / 16, NHEADS, BATCH), 256, ATTN_SMEM>>>(
        qp, kv, weights, attn);
    gemm_nt_bias<<<dim3(D_MODEL / 64, M_TOTAL / 64), 256>>>(
        attn, dense_w, dense_b, out, M_TOTAL, D_MODEL, D_MODEL);
}

// round 7
// speedup vs baseline: 1.8993x; 1.2719x over previous
#include <cuda_runtime.h>
#include <cstdint>
#include <cstddef>

#define D_MODEL 1024
#define NHEADS  16
#define DEPTH   64
#define BATCH   2
#define SEQ     2048
#define M_TOTAL (BATCH * SEQ)

__device__ float g_Qp[(size_t)M_TOTAL * D_MODEL];
__device__ float g_KV[(size_t)M_TOTAL * 2 * DEPTH];
__device__ float g_attn[(size_t)M_TOTAL * D_MODEL];

// ---------------------------------------------------------------------------
// helpers (baseline sm_80-level PTX, legal on compute_103)
// ---------------------------------------------------------------------------
__device__ __forceinline__ uint32_t smem_u32(const void* p) {
    uint32_t a;
    asm("{ .reg .u64 t; cvta.to.shared.u64 t, %1; cvt.u32.u64 %0, t; }" : "=r"(a) : "l"(p));
    return a;
}
__device__ __forceinline__ uint32_t pack_bf16(float lo, float hi) {
    uint32_t r;
    asm("cvt.rn.bf16x2.f32 %0, %1, %2;" : "=r"(r) : "f"(hi), "f"(lo));
    return r;
}
__device__ __forceinline__ void mma_bf16(float* c, const uint32_t* a, const uint32_t* b) {
    asm volatile("mma.sync.aligned.m16n8k16.row.col.f32.bf16.bf16.f32 "
        "{%0,%1,%2,%3}, {%4,%5,%6,%7}, {%8,%9}, {%0,%1,%2,%3};"
        : "+f"(c[0]), "+f"(c[1]), "+f"(c[2]), "+f"(c[3])
        : "r"(a[0]), "r"(a[1]), "r"(a[2]), "r"(a[3]), "r"(b[0]), "r"(b[1]));
}
#define LDSM_X4(r0, r1, r2, r3, addr) \
    asm volatile("ldmatrix.sync.aligned.m8n8.x4.shared.b16 {%0,%1,%2,%3}, [%4];" \
        : "=r"(r0), "=r"(r1), "=r"(r2), "=r"(r3) : "r"(addr))
#define LDSM_X2T(r0, r1, addr) \
    asm volatile("ldmatrix.sync.aligned.m8n8.x2.trans.shared.b16 {%0,%1}, [%2];" \
        : "=r"(r0), "=r"(r1) : "r"(addr))

// split one float4 into bf16 hi (truncate) + mid (rn residual), store 2+2 words
__device__ __forceinline__ void split_store(uint32_t* whi, uint32_t* wmid, int wi, float4 v) {
    uint32_t b0 = __float_as_uint(v.x), b1 = __float_as_uint(v.y);
    uint32_t b2 = __float_as_uint(v.z), b3 = __float_as_uint(v.w);
    uint32_t h0 = __byte_perm(b0, b1, 0x7632);
    uint32_t h1 = __byte_perm(b2, b3, 0x7632);
    float m0 = v.x - __uint_as_float(b0 & 0xFFFF0000u);
    float m1 = v.y - __uint_as_float(b1 & 0xFFFF0000u);
    float m2 = v.z - __uint_as_float(b2 & 0xFFFF0000u);
    float m3 = v.w - __uint_as_float(b3 & 0xFFFF0000u);
    *(uint2*)(whi + wi)  = make_uint2(h0, h1);
    *(uint2*)(wmid + wi) = make_uint2(pack_bf16(m0, m1), pack_bf16(m2, m3));
}

// ===========================================================================
// Tensor-core GEMM: C[M,N] = A[M,K] @ W[N,K]^T + bias[N], bf16x3.
// 128x128 tile, BK=32, 256 threads, warp tile 32x64 (warps 4m x 2n).
// Smem rows stride 20 words (16 data + 4 pad -> 32 distinct banks for frags).
// ===========================================================================
#define GSTRIDE 20

__global__ __launch_bounds__(256) void gemm_tc(
    const float* __restrict__ A, const float* __restrict__ W,
    const float* __restrict__ bias, float* __restrict__ C,
    int M, int N, int K)
{
    __shared__ uint32_t Ahi[128 * GSTRIDE], Amid[128 * GSTRIDE];
    __shared__ uint32_t Bhi[128 * GSTRIDE], Bmid[128 * GSTRIDE];
    const int tid = threadIdx.x, wid = tid >> 5, lane = tid & 31;
    const int gid = lane >> 2, tig = lane & 3;
    const int warp_m = wid & 3, warp_n = wid >> 2;
    const int m0 = blockIdx.y * 128, n0 = blockIdx.x * 128;

    float acc[2][8][4];
#pragma unroll
    for (int mt = 0; mt < 2; mt++)
#pragma unroll
        for (int nt = 0; nt < 8; nt++)
#pragma unroll
            for (int j = 0; j < 4; j++) acc[mt][nt][j] = 0.f;

    for (int k0 = 0; k0 < K; k0 += 32) {
        __syncthreads();
#pragma unroll
        for (int i = 0; i < 4; i++) {
            int e = tid + i * 256;
            int r = e >> 3, w8 = e & 7;
            float4 va = *(const float4*)(A + (size_t)(m0 + r) * K + k0 + w8 * 4);
            split_store(Ahi, Amid, r * GSTRIDE + w8 * 2, va);
            float4 vb = *(const float4*)(W + (size_t)(n0 + r) * K + k0 + w8 * 4);
            split_store(Bhi, Bmid, r * GSTRIDE + w8 * 2, vb);
        }
        __syncthreads();
#pragma unroll
        for (int ds = 0; ds < 2; ds++) {
            uint32_t ah[2][4], am[2][4];
#pragma unroll
            for (int mt = 0; mt < 2; mt++) {
                int r0 = (warp_m * 32 + mt * 16 + gid) * GSTRIDE + ds * 8 + tig;
                int r1 = r0 + 8 * GSTRIDE;
                ah[mt][0] = Ahi[r0];     ah[mt][1] = Ahi[r1];
                ah[mt][2] = Ahi[r0 + 4]; ah[mt][3] = Ahi[r1 + 4];
                am[mt][0] = Amid[r0];     am[mt][1] = Amid[r1];
                am[mt][2] = Amid[r0 + 4]; am[mt][3] = Amid[r1 + 4];
            }
#pragma unroll
            for (int nt = 0; nt < 8; nt++) {
                int wi = (warp_n * 64 + nt * 8 + gid) * GSTRIDE + ds * 8 + tig;
                uint32_t bh[2] = { Bhi[wi], Bhi[wi + 4] };
                uint32_t bm[2] = { Bmid[wi], Bmid[wi + 4] };
#pragma unroll
                for (int mt = 0; mt < 2; mt++) {
                    mma_bf16(acc[mt][nt], ah[mt], bh);   // hi*hi
                    mma_bf16(acc[mt][nt], am[mt], bh);   // mid*hi
                    mma_bf16(acc[mt][nt], ah[mt], bm);   // hi*mid
                }
            }
        }
    }
#pragma unroll
    for (int mt = 0; mt < 2; mt++) {
        int row = m0 + warp_m * 32 + mt * 16 + gid;
#pragma unroll
        for (int nt = 0; nt < 8; nt++) {
            int col = n0 + warp_n * 64 + nt * 8 + tig * 2;
            float2 bv = *(const float2*)&bias[col];
            *(float2*)&C[(size_t)row * N + col] =
                make_float2(acc[mt][nt][0] + bv.x, acc[mt][nt][1] + bv.y);
            *(float2*)&C[(size_t)(row + 8) * N + col] =
                make_float2(acc[mt][nt][2] + bv.x, acc[mt][nt][3] + bv.y);
        }
    }
}

// ---------------------------------------------------------------------------
// attn smem layout (identical to R6)
// ---------------------------------------------------------------------------
#define LSTRIDE 2052
#define KSTRIDE 36
#define PSTRIDE 132
#define OFF_LOG  0
#define OFF_KHI  (16 * LSTRIDE * 4)
#define OFF_KMID (OFF_KHI  + 128 * KSTRIDE * 4)
#define OFF_QHI  (OFF_KMID + 128 * KSTRIDE * 4)
#define OFF_QMID (OFF_QHI  + 16 * KSTRIDE * 4)
#define OFF_PHI  (OFF_QMID + 16 * KSTRIDE * 4)
#define OFF_PMID (OFF_PHI  + 16 * PSTRIDE * 4)
#define ATTN_SMEM (OFF_PMID + 16 * PSTRIDE * 4)     // 189696

// stage 128 KV rows (doff=0 -> K, doff=64 -> V), 512 threads
__device__ __forceinline__ void stage_kv512(const float* kvb, int kc, int doff,
                                            uint32_t* whi, uint32_t* wmid, int tid) {
#pragma unroll
    for (int i = 0; i < 4; i++) {
        int e = tid + i * 512;
        int r = e >> 4, c4 = (e & 15) * 4;
        float4 v = *(const float4*)(kvb + (size_t)(kc + r) * 128 + doff + c4);
        split_store(whi, wmid, r * KSTRIDE + c4 / 2, v);
    }
}

// ===========================================================================
// Attention bf16x3, 512 threads (16 warps). CTA = 16 q rows of one (b,h).
// Phase 1: warp w owns k-rows [w*8, w*8+8) per 128-chunk.
// Phase 2: warp w owns softmax row w.
// Phase 3: warp pair (w, w^1) splits k halves for d-group w>>1; smem reduce.
// ===========================================================================
__global__ __launch_bounds__(512, 1) void attn_mma(
    const float* __restrict__ Qp, const float* __restrict__ KV,
    float* __restrict__ Wout, float* __restrict__ Aout)
{
    extern __shared__ char sm[];
    const int tid = threadIdx.x, wid = tid >> 5, lane = tid & 31;
    const int gid = lane >> 2, tig = lane & 3;
    const int b = blockIdx.z, h = blockIdx.y, q0 = blockIdx.x * 16;
    const uint32_t sb = smem_u32(sm);

    float*    logits = (float*)(sm + OFF_LOG);
    uint32_t* kw_hi  = (uint32_t*)(sm + OFF_KHI);
    uint32_t* kw_mid = (uint32_t*)(sm + OFF_KMID);
    uint32_t* qw_hi  = (uint32_t*)(sm + OFF_QHI);
    uint32_t* qw_mid = (uint32_t*)(sm + OFF_QMID);
    uint32_t* pw_hi  = (uint32_t*)(sm + OFF_PHI);
    uint32_t* pw_mid = (uint32_t*)(sm + OFF_PMID);
    const float* kvb = KV + (size_t)b * SEQ * 128;

    // ---- stage Q (x0.125, exact) ----
    if (tid < 256) {
        int r = tid >> 4, c4 = (tid & 15) * 4;
        float4 v = *(const float4*)(Qp + (size_t)(b * SEQ + q0 + r) * D_MODEL + h * DEPTH + c4);
        v.x *= 0.125f; v.y *= 0.125f; v.z *= 0.125f; v.w *= 0.125f;
        split_store(qw_hi, qw_mid, r * KSTRIDE + c4 / 2, v);
    }
    __syncthreads();

    // persistent Q fragments
    uint32_t qh[4][4], qm[4][4];
#pragma unroll
    for (int ds = 0; ds < 4; ds++) {
        int w0 = gid * KSTRIDE + ds * 8 + tig;
        int w1 = (gid + 8) * KSTRIDE + ds * 8 + tig;
        qh[ds][0] = qw_hi[w0];  qh[ds][1] = qw_hi[w1];
        qh[ds][2] = qw_hi[w0 + 4]; qh[ds][3] = qw_hi[w1 + 4];
        qm[ds][0] = qw_mid[w0]; qm[ds][1] = qw_mid[w1];
        qm[ds][2] = qw_mid[w0 + 4]; qm[ds][3] = qw_mid[w1 + 4];
    }

    // ---- Phase 1: logits ----
    for (int kc = 0; kc < SEQ; kc += 128) {
        __syncthreads();
        stage_kv512(kvb, kc, 0, kw_hi, kw_mid, tid);
        __syncthreads();
        const int krow0 = wid * 8;
        float c[4] = {0.f, 0.f, 0.f, 0.f};
#pragma unroll
        for (int ds = 0; ds < 4; ds++) {
            int wi = (krow0 + gid) * KSTRIDE + ds * 8 + tig;
            uint32_t bh[2] = { kw_hi[wi],  kw_hi[wi + 4]  };
            uint32_t bm[2] = { kw_mid[wi], kw_mid[wi + 4] };
            mma_bf16(c, qh[ds], bh);
            mma_bf16(c, qm[ds], bh);
            mma_bf16(c, qh[ds], bm);
        }
        int col = kc + krow0 + tig * 2;
        *(float2*)&logits[gid * LSTRIDE + col]       = make_float2(c[0], c[1]);
        *(float2*)&logits[(gid + 8) * LSTRIDE + col] = make_float2(c[2], c[3]);
    }
    __syncthreads();

    // ---- Phase 2: softmax row wid ----
    {
        float* row = logits + wid * LSTRIDE;
        float m = -1e30f;
        for (int k = lane; k < SEQ; k += 32) m = fmaxf(m, row[k]);
#pragma unroll
        for (int o = 16; o; o >>= 1) m = fmaxf(m, __shfl_xor_sync(0xffffffffu, m, o));
        float s = 0.f;
        for (int k = lane; k < SEQ; k += 32) {
            float e = __expf(row[k] - m);
            row[k] = e;
            s += e;
        }
#pragma unroll
        for (int o = 16; o; o >>= 1) s += __shfl_xor_sync(0xffffffffu, s, o);
        float inv = 1.f / s;
        float* wrow = Wout + (((size_t)(b * NHEADS + h)) * SEQ + (q0 + wid)) * SEQ;
        for (int k = lane; k < SEQ; k += 32) {
            float p = row[k] * inv;
            row[k] = p;
            wrow[k] = p;
        }
    }

    // ---- Phase 3: PV, warp pair splits k halves ----
    const int kh = wid & 1, dgrp = wid >> 1;
    const uint32_t pA  = sb + OFF_PHI +
        (uint32_t)(((lane & 7) + 8 * ((lane >> 3) & 1)) * (PSTRIDE * 4)) + ((lane >> 4) * 16);
    const uint32_t pAm = pA + (OFF_PMID - OFF_PHI);
    const uint32_t vR  = sb + OFF_KHI + (uint32_t)((lane & 15) * (KSTRIDE * 4)) + (uint32_t)(dgrp * 16);
    const uint32_t vRm = vR + (OFF_KMID - OFF_KHI);

    float acc[4] = {0.f, 0.f, 0.f, 0.f};

    for (int kc = 0; kc < SEQ; kc += 128) {
        __syncthreads();
        stage_kv512(kvb, kc, 64, kw_hi, kw_mid, tid);   // V chunk
        {   // convert P chunk [16][128] -> bf16 hi/mid (1 float4/thread)
            int q = tid >> 5, c0 = (tid & 31) * 4;
            float4 v = *(const float4*)&logits[q * LSTRIDE + kc + c0];
            split_store(pw_hi, pw_mid, q * PSTRIDE + c0 / 2, v);
        }
        __syncthreads();
#pragma unroll
        for (int kk = 0; kk < 4; kk++) {
            int ks = kh * 4 + kk;
            uint32_t ah[4], am[4], bh[2], bm[2];
            LDSM_X4(ah[0], ah[1], ah[2], ah[3], pA + ks * 32);
            LDSM_X4(am[0], am[1], am[2], am[3], pAm + ks * 32);
            LDSM_X2T(bh[0], bh[1], vR + ks * 16 * (KSTRIDE * 4));
            LDSM_X2T(bm[0], bm[1], vRm + ks * 16 * (KSTRIDE * 4));
            mma_bf16(acc, ah, bh);
            mma_bf16(acc, am, bh);
            mma_bf16(acc, ah, bm);
        }
    }

    // cross-half reduction through smem (reuse logits region)
    float* red = logits;
    __syncthreads();
    *(float4*)&red[wid * 128 + lane * 4] = make_float4(acc[0], acc[1], acc[2], acc[3]);
    __syncthreads();
    if (kh == 0) {
        float4 o = *(const float4*)&red[(wid + 1) * 128 + lane * 4];
        acc[0] += o.x; acc[1] += o.y; acc[2] += o.z; acc[3] += o.w;
        int dcol = h * DEPTH + dgrp * 8 + tig * 2;
        *(float2*)&Aout[(size_t)(b * SEQ + q0 + gid)     * D_MODEL + dcol] = make_float2(acc[0], acc[1]);
        *(float2*)&Aout[(size_t)(b * SEQ + q0 + gid + 8) * D_MODEL + dcol] = make_float2(acc[2], acc[3]);
    }
}

// --------------------- fp32 GEMM (kept for KV projection) ------------------
__global__ __launch_bounds__(256) void gemm_nt_bias(
    const float* __restrict__ A, const float* __restrict__ W,
    const float* __restrict__ bias, float* __restrict__ C,
    int M, int N, int K)
{
    __shared__ float As[16][68];
    __shared__ float Ws[16][68];
    int tid = threadIdx.x;
    int m0 = blockIdx.y * 64, n0 = blockIdx.x * 64;
    int lr = tid >> 2, lq = tid & 3;
    int tx = tid & 15, ty = tid >> 4;
    float acc[4][4];
#pragma unroll
    for (int i = 0; i < 4; i++)
#pragma unroll
        for (int j = 0; j < 4; j++) acc[i][j] = 0.f;
    const float* Aptr = A + (size_t)(m0 + lr) * K + lq * 4;
    const float* Wptr = W + (size_t)(n0 + lr) * K + lq * 4;
    for (int k0 = 0; k0 < K; k0 += 16) {
        float4 av = *(const float4*)(Aptr + k0);
        float4 wv = *(const float4*)(Wptr + k0);
        __syncthreads();
        As[lq*4+0][lr] = av.x; As[lq*4+1][lr] = av.y; As[lq*4+2][lr] = av.z; As[lq*4+3][lr] = av.w;
        Ws[lq*4+0][lr] = wv.x; Ws[lq*4+1][lr] = wv.y; Ws[lq*4+2][lr] = wv.z; Ws[lq*4+3][lr] = wv.w;
        __syncthreads();
#pragma unroll
        for (int kk = 0; kk < 16; kk++) {
            float4 a = *(const float4*)&As[kk][ty * 4];
            float4 w = *(const float4*)&Ws[kk][tx * 4];
            acc[0][0] += a.x*w.x; acc[0][1] += a.x*w.y; acc[0][2] += a.x*w.z; acc[0][3] += a.x*w.w;
            acc[1][0] += a.y*w.x; acc[1][1] += a.y*w.y; acc[1][2] += a.y*w.z; acc[1][3] += a.y*w.w;
            acc[2][0] += a.z*w.x; acc[2][1] += a.z*w.y; acc[2][2] += a.z*w.z; acc[2][3] += a.z*w.w;
            acc[3][0] += a.w*w.x; acc[3][1] += a.w*w.y; acc[3][2] += a.w*w.z; acc[3][3] += a.w*w.w;
        }
    }
    float4 bv = *(const float4*)&bias[n0 + tx * 4];
#pragma unroll
    for (int i = 0; i < 4; i++) {
        float4 o;
        o.x = acc[i][0] + bv.x; o.y = acc[i][1] + bv.y;
        o.z = acc[i][2] + bv.z; o.w = acc[i][3] + bv.w;
        *(float4*)&C[(size_t)(m0 + ty * 4 + i) * N + n0 + tx * 4] = o;
    }
}

// ---------------------------------------------------------------------------
extern "C" void kernel_launch(void* const* d_in, const int* in_sizes, int n_in,
                              void* d_out, int out_size)
{
    const float* Q       = (const float*)d_in[0];
    const float* K       = (const float*)d_in[1];
    // d_in[2] = V (unused: reference derives V from the KV projection)
    const float* WQ_w    = (const float*)d_in[3];
    const float* WQ_b    = (const float*)d_in[4];
    const float* WKV_w   = (const float*)d_in[5];
    const float* WKV_b   = (const float*)d_in[6];
    const float* dense_w = (const float*)d_in[7];
    const float* dense_b = (const float*)d_in[8];

    float* out     = (float*)d_out;
    float* weights = out + (size_t)M_TOTAL * D_MODEL;

    float *qp, *kv, *attn;
    cudaGetSymbolAddress((void**)&qp,   g_Qp);
    cudaGetSymbolAddress((void**)&kv,   g_KV);
    cudaGetSymbolAddress((void**)&attn, g_attn);

    cudaFuncSetAttribute(attn_mma, cudaFuncAttributeMaxDynamicSharedMemorySize, ATTN_SMEM);

    // 1) Qp = Q @ WQ_w^T + b   (tensor core bf16x3)
    gemm_tc<<<dim3(D_MODEL / 128, M_TOTAL / 128), 256>>>(
        Q, WQ_w, WQ_b, qp, M_TOTAL, D_MODEL, D_MODEL);
    // 2) KV = K @ WKV_w^T + b  (exact fp32, feeds softmax)
    gemm_nt_bias<<<dim3((2 * DEPTH) / 64, M_TOTAL / 64), 256>>>(
        K, WKV_w, WKV_b, kv, M_TOTAL, 2 * DEPTH, D_MODEL);
    // 3) attention
    attn_mma<<<dim3(SEQ / 16, NHEADS, BATCH), 512, ATTN_SMEM>>>(
        qp, kv, weights, attn);
    // 4) out = attn @ dense_w^T + b  (tensor core bf16x3)
    gemm_tc<<<dim3(D_MODEL / 128, M_TOTAL / 128), 256>>>(
        attn, dense_w, dense_b, out, M_TOTAL, D_MODEL, D_MODEL);
}

// round 10
// speedup vs baseline: 2.0528x; 1.0808x over previous
#include <cuda_runtime.h>
#include <cstdint>
#include <cstddef>

#define D_MODEL 1024
#define NHEADS  16
#define DEPTH   64
#define BATCH   2
#define SEQ     2048
#define M_TOTAL (BATCH * SEQ)

__device__ float g_Qp[(size_t)M_TOTAL * D_MODEL];
__device__ float g_KV[(size_t)M_TOTAL * 2 * DEPTH];
__device__ float g_attn[(size_t)M_TOTAL * D_MODEL];
// pre-split bf16 hi/mid (packed 2 per word)
__device__ uint32_t g_Qh[(size_t)M_TOTAL * 512];
__device__ uint32_t g_Qm[(size_t)M_TOTAL * 512];
__device__ uint32_t g_KVh[(size_t)M_TOTAL * 64];
__device__ uint32_t g_KVm[(size_t)M_TOTAL * 64];

// ---------------------------------------------------------------------------
// helpers (baseline sm_80-level PTX, legal on compute_103)
// ---------------------------------------------------------------------------
__device__ __forceinline__ uint32_t smem_u32(const void* p) {
    uint32_t a;
    asm("{ .reg .u64 t; cvta.to.shared.u64 t, %1; cvt.u32.u64 %0, t; }" : "=r"(a) : "l"(p));
    return a;
}
__device__ __forceinline__ uint32_t pack_bf16(float lo, float hi) {
    uint32_t r;
    asm("cvt.rn.bf16x2.f32 %0, %1, %2;" : "=r"(r) : "f"(hi), "f"(lo));
    return r;
}
__device__ __forceinline__ void mma_bf16(float* c, const uint32_t* a, const uint32_t* b) {
    asm volatile("mma.sync.aligned.m16n8k16.row.col.f32.bf16.bf16.f32 "
        "{%0,%1,%2,%3}, {%4,%5,%6,%7}, {%8,%9}, {%0,%1,%2,%3};"
        : "+f"(c[0]), "+f"(c[1]), "+f"(c[2]), "+f"(c[3])
        : "r"(a[0]), "r"(a[1]), "r"(a[2]), "r"(a[3]), "r"(b[0]), "r"(b[1]));
}
#define LDSM_X4(r0, r1, r2, r3, addr) \
    asm volatile("ldmatrix.sync.aligned.m8n8.x4.shared.b16 {%0,%1,%2,%3}, [%4];" \
        : "=r"(r0), "=r"(r1), "=r"(r2), "=r"(r3) : "r"(addr))
#define LDSM_X2T(r0, r1, addr) \
    asm volatile("ldmatrix.sync.aligned.m8n8.x2.trans.shared.b16 {%0,%1}, [%2];" \
        : "=r"(r0), "=r"(r1) : "r"(addr))
#define CP_ASYNC16(dst, src) \
    asm volatile("cp.async.cg.shared.global [%0], [%1], 16;" :: "r"(dst), "l"(src))
#define CP_COMMIT() asm volatile("cp.async.commit_group;" ::: "memory")
#define CP_WAIT1()  asm volatile("cp.async.wait_group 1;" ::: "memory")
#define CP_WAIT0()  asm volatile("cp.async.wait_group 0;" ::: "memory")

// split one float4 into bf16 hi (truncate) + mid (rn residual), store 2+2 words
__device__ __forceinline__ void split_store(uint32_t* whi, uint32_t* wmid, int wi, float4 v) {
    uint32_t b0 = __float_as_uint(v.x), b1 = __float_as_uint(v.y);
    uint32_t b2 = __float_as_uint(v.z), b3 = __float_as_uint(v.w);
    uint32_t h0 = __byte_perm(b0, b1, 0x7632);
    uint32_t h1 = __byte_perm(b2, b3, 0x7632);
    float m0 = v.x - __uint_as_float(b0 & 0xFFFF0000u);
    float m1 = v.y - __uint_as_float(b1 & 0xFFFF0000u);
    float m2 = v.z - __uint_as_float(b2 & 0xFFFF0000u);
    float m3 = v.w - __uint_as_float(b3 & 0xFFFF0000u);
    *(uint2*)(whi + wi)  = make_uint2(h0, h1);
    *(uint2*)(wmid + wi) = make_uint2(pack_bf16(m0, m1), pack_bf16(m2, m3));
}

// ---------------------------------------------------------------------------
// prep: split fp32 array into bf16 hi/mid packed words (scale folded; exact
// for power-of-two scales)
// ---------------------------------------------------------------------------
__global__ __launch_bounds__(256) void split_pre(
    const float4* __restrict__ src, uint2* __restrict__ dh, uint2* __restrict__ dm,
    int n4, float scale)
{
    int i = blockIdx.x * blockDim.x + threadIdx.x;
    if (i >= n4) return;
    float4 v = src[i];
    v.x *= scale; v.y *= scale; v.z *= scale; v.w *= scale;
    uint32_t b0 = __float_as_uint(v.x), b1 = __float_as_uint(v.y);
    uint32_t b2 = __float_as_uint(v.z), b3 = __float_as_uint(v.w);
    dh[i] = make_uint2(__byte_perm(b0, b1, 0x7632), __byte_perm(b2, b3, 0x7632));
    float m0 = v.x - __uint_as_float(b0 & 0xFFFF0000u);
    float m1 = v.y - __uint_as_float(b1 & 0xFFFF0000u);
    float m2 = v.z - __uint_as_float(b2 & 0xFFFF0000u);
    float m3 = v.w - __uint_as_float(b3 & 0xFFFF0000u);
    dm[i] = make_uint2(pack_bf16(m0, m1), pack_bf16(m2, m3));
}

// ===========================================================================
// Tensor-core GEMM: bf16x3, 128x128 tile, BK=32, 256 threads.
// ===========================================================================
#define GSTRIDE 20

__global__ __launch_bounds__(256) void gemm_tc(
    const float* __restrict__ A, const float* __restrict__ W,
    const float* __restrict__ bias, float* __restrict__ C,
    int M, int N, int K)
{
    __shared__ uint32_t Ahi[128 * GSTRIDE], Amid[128 * GSTRIDE];
    __shared__ uint32_t Bhi[128 * GSTRIDE], Bmid[128 * GSTRIDE];
    const int tid = threadIdx.x, wid = tid >> 5, lane = tid & 31;
    const int gid = lane >> 2, tig = lane & 3;
    const int warp_m = wid & 3, warp_n = wid >> 2;
    const int m0 = blockIdx.y * 128, n0 = blockIdx.x * 128;

    float acc[2][8][4];
#pragma unroll
    for (int mt = 0; mt < 2; mt++)
#pragma unroll
        for (int nt = 0; nt < 8; nt++)
#pragma unroll
            for (int j = 0; j < 4; j++) acc[mt][nt][j] = 0.f;

    for (int k0 = 0; k0 < K; k0 += 32) {
        __syncthreads();
#pragma unroll
        for (int i = 0; i < 4; i++) {
            int e = tid + i * 256;
            int r = e >> 3, w8 = e & 7;
            float4 va = *(const float4*)(A + (size_t)(m0 + r) * K + k0 + w8 * 4);
            split_store(Ahi, Amid, r * GSTRIDE + w8 * 2, va);
            float4 vb = *(const float4*)(W + (size_t)(n0 + r) * K + k0 + w8 * 4);
            split_store(Bhi, Bmid, r * GSTRIDE + w8 * 2, vb);
        }
        __syncthreads();
#pragma unroll
        for (int ds = 0; ds < 2; ds++) {
            uint32_t ah[2][4], am[2][4];
#pragma unroll
            for (int mt = 0; mt < 2; mt++) {
                int r0 = (warp_m * 32 + mt * 16 + gid) * GSTRIDE + ds * 8 + tig;
                int r1 = r0 + 8 * GSTRIDE;
                ah[mt][0] = Ahi[r0];     ah[mt][1] = Ahi[r1];
                ah[mt][2] = Ahi[r0 + 4]; ah[mt][3] = Ahi[r1 + 4];
                am[mt][0] = Amid[r0];     am[mt][1] = Amid[r1];
                am[mt][2] = Amid[r0 + 4]; am[mt][3] = Amid[r1 + 4];
            }
#pragma unroll
            for (int nt = 0; nt < 8; nt++) {
                int wi = (warp_n * 64 + nt * 8 + gid) * GSTRIDE + ds * 8 + tig;
                uint32_t bh[2] = { Bhi[wi], Bhi[wi + 4] };
                uint32_t bm[2] = { Bmid[wi], Bmid[wi + 4] };
#pragma unroll
                for (int mt = 0; mt < 2; mt++) {
                    mma_bf16(acc[mt][nt], ah[mt], bh);
                    mma_bf16(acc[mt][nt], am[mt], bh);
                    mma_bf16(acc[mt][nt], ah[mt], bm);
                }
            }
        }
    }
#pragma unroll
    for (int mt = 0; mt < 2; mt++) {
        int row = m0 + warp_m * 32 + mt * 16 + gid;
#pragma unroll
        for (int nt = 0; nt < 8; nt++) {
            int col = n0 + warp_n * 64 + nt * 8 + tig * 2;
            float2 bv = *(const float2*)&bias[col];
            *(float2*)&C[(size_t)row * N + col] =
                make_float2(acc[mt][nt][0] + bv.x, acc[mt][nt][1] + bv.y);
            *(float2*)&C[(size_t)(row + 8) * N + col] =
                make_float2(acc[mt][nt][2] + bv.x, acc[mt][nt][3] + bv.y);
        }
    }
}

// ---------------------------------------------------------------------------
// attn smem layout: logits + DOUBLE-BUFFERED K/V stages + Q + P
// ---------------------------------------------------------------------------
#define LSTRIDE 2052
#define KSTRIDE 36          // words per K/V row (32 data + 4 pad); 144 B
#define PSTRIDE 132
#define OFF_LOG   0
#define OFF_K0HI  (16 * LSTRIDE * 4)                 // 131328
#define OFF_K0MID (OFF_K0HI  + 128 * KSTRIDE * 4)    // +18432
#define OFF_K1HI  (OFF_K0MID + 128 * KSTRIDE * 4)
#define OFF_K1MID (OFF_K1HI  + 128 * KSTRIDE * 4)
#define OFF_QHI   (OFF_K1MID + 128 * KSTRIDE * 4)    // 205056
#define OFF_QMID  (OFF_QHI   + 16 * KSTRIDE * 4)
#define OFF_PHI   (OFF_QMID  + 16 * KSTRIDE * 4)     // 209664
#define OFF_PMID  (OFF_PHI   + 16 * PSTRIDE * 4)
#define ATTN_SMEM (OFF_PMID  + 16 * PSTRIDE * 4)     // 226560

// async-prefetch one 128-row K or V chunk (bf16 hi/mid) into a stage.
// voff: 0 = K half, 32 = V half (word offset in the 64-word KV row).
__device__ __forceinline__ void prefetch_kv(
    const uint32_t* __restrict__ KVh, const uint32_t* __restrict__ KVm,
    int rowbase, int voff, uint32_t dhi, uint32_t dmid, int tid)
{
#pragma unroll
    for (int i = 0; i < 4; i++) {
        int e = tid + i * 512;
        int r = e >> 4, t = e & 15;
        int w8 = t & 7;
        const uint32_t* src = ((t & 8) ? KVm : KVh) + (size_t)(rowbase + r) * 64 + voff + w8 * 4;
        uint32_t dst = ((t & 8) ? dmid : dhi) + (uint32_t)(r * 144 + w8 * 16);
        CP_ASYNC16(dst, src);
    }
}

// ===========================================================================
// Attention bf16x3, 512 threads, cp.async double-buffered staging.
// ===========================================================================
__global__ __launch_bounds__(512, 1) void attn_mma(
    const uint32_t* __restrict__ Qh, const uint32_t* __restrict__ Qm,
    const uint32_t* __restrict__ KVh, const uint32_t* __restrict__ KVm,
    float* __restrict__ Wout, float* __restrict__ Aout)
{
    extern __shared__ char sm[];
    const int tid = threadIdx.x, wid = tid >> 5, lane = tid & 31;
    const int gid = lane >> 2, tig = lane & 3;
    const int b = blockIdx.z, h = blockIdx.y, q0 = blockIdx.x * 16;
    const uint32_t sb = smem_u32(sm);
    const int rb = b * SEQ;

    float*    logits = (float*)(sm + OFF_LOG);
    uint32_t* qw_hi  = (uint32_t*)(sm + OFF_QHI);
    uint32_t* qw_mid = (uint32_t*)(sm + OFF_QMID);
    uint32_t* pw_hi  = (uint32_t*)(sm + OFF_PHI);
    uint32_t* pw_mid = (uint32_t*)(sm + OFF_PMID);

    // kick off K chunk 0 prefetch immediately
    prefetch_kv(KVh, KVm, rb, 0, sb + OFF_K0HI, sb + OFF_K0MID, tid);
    CP_COMMIT();

    // ---- stage Q (pre-scaled, pre-split) ----
    if (tid < 256) {
        int r = tid >> 4, c4 = (tid & 15) * 4;
        size_t gw = (size_t)(rb + q0 + r) * 512 + h * 32 + c4 / 2;
        *(uint2*)&qw_hi[r * KSTRIDE + c4 / 2]  = *(const uint2*)&Qh[gw];
        *(uint2*)&qw_mid[r * KSTRIDE + c4 / 2] = *(const uint2*)&Qm[gw];
    }
    __syncthreads();

    uint32_t qh[4][4], qm[4][4];
#pragma unroll
    for (int ds = 0; ds < 4; ds++) {
        int w0 = gid * KSTRIDE + ds * 8 + tig;
        int w1 = (gid + 8) * KSTRIDE + ds * 8 + tig;
        qh[ds][0] = qw_hi[w0];  qh[ds][1] = qw_hi[w1];
        qh[ds][2] = qw_hi[w0 + 4]; qh[ds][3] = qw_hi[w1 + 4];
        qm[ds][0] = qw_mid[w0]; qm[ds][1] = qw_mid[w1];
        qm[ds][2] = qw_mid[w0 + 4]; qm[ds][3] = qw_mid[w1 + 4];
    }

    // ---- Phase 1: logits (pipelined K staging) ----
    for (int ch = 0; ch < 16; ch++) {
        if (ch < 15) {
            uint32_t dh = ((ch + 1) & 1) ? (sb + OFF_K1HI) : (sb + OFF_K0HI);
            uint32_t dm = ((ch + 1) & 1) ? (sb + OFF_K1MID) : (sb + OFF_K0MID);
            prefetch_kv(KVh, KVm, rb + (ch + 1) * 128, 0, dh, dm, tid);
        }
        CP_COMMIT();
        CP_WAIT1();
        __syncthreads();
        const uint32_t* kw_hi  = (const uint32_t*)(sm + ((ch & 1) ? OFF_K1HI : OFF_K0HI));
        const uint32_t* kw_mid = (const uint32_t*)(sm + ((ch & 1) ? OFF_K1MID : OFF_K0MID));
        const int krow0 = wid * 8;
        float c[4] = {0.f, 0.f, 0.f, 0.f};
#pragma unroll
        for (int ds = 0; ds < 4; ds++) {
            int wi = (krow0 + gid) * KSTRIDE + ds * 8 + tig;
            uint32_t bh[2] = { kw_hi[wi],  kw_hi[wi + 4]  };
            uint32_t bm[2] = { kw_mid[wi], kw_mid[wi + 4] };
            mma_bf16(c, qh[ds], bh);
            mma_bf16(c, qm[ds], bh);
            mma_bf16(c, qh[ds], bm);
        }
        int col = ch * 128 + krow0 + tig * 2;
        *(float2*)&logits[gid * LSTRIDE + col]       = make_float2(c[0], c[1]);
        *(float2*)&logits[(gid + 8) * LSTRIDE + col] = make_float2(c[2], c[3]);
        __syncthreads();
    }
    CP_WAIT0();

    // ---- Phase 2: softmax row wid ----
    {
        float* row = logits + wid * LSTRIDE;
        float m = -1e30f;
        for (int k = lane; k < SEQ; k += 32) m = fmaxf(m, row[k]);
#pragma unroll
        for (int o = 16; o; o >>= 1) m = fmaxf(m, __shfl_xor_sync(0xffffffffu, m, o));
        float s = 0.f;
        for (int k = lane; k < SEQ; k += 32) {
            float e = __expf(row[k] - m);
            row[k] = e;
            s += e;
        }
#pragma unroll
        for (int o = 16; o; o >>= 1) s += __shfl_xor_sync(0xffffffffu, s, o);
        float inv = 1.f / s;
        float* wrow = Wout + (((size_t)(b * NHEADS + h)) * SEQ + (q0 + wid)) * SEQ;
        for (int k = lane; k < SEQ; k += 32) {
            float p = row[k] * inv;
            row[k] = p;
            wrow[k] = p;
        }
    }
    __syncthreads();

    // ---- Phase 3: PV (pipelined V staging), warp pair splits k halves ----
    prefetch_kv(KVh, KVm, rb, 32, sb + OFF_K0HI, sb + OFF_K0MID, tid);
    CP_COMMIT();

    const int kh = wid & 1, dgrp = wid >> 1;
    const uint32_t pA  = sb + OFF_PHI +
        (uint32_t)(((lane & 7) + 8 * ((lane >> 3) & 1)) * (PSTRIDE * 4)) + ((lane >> 4) * 16);
    const uint32_t pAm = pA + (OFF_PMID - OFF_PHI);

    float acc[4] = {0.f, 0.f, 0.f, 0.f};

    for (int ch = 0; ch < 16; ch++) {
        if (ch < 15) {
            uint32_t dh = ((ch + 1) & 1) ? (sb + OFF_K1HI) : (sb + OFF_K0HI);
            uint32_t dm = ((ch + 1) & 1) ? (sb + OFF_K1MID) : (sb + OFF_K0MID);
            prefetch_kv(KVh, KVm, rb + (ch + 1) * 128, 32, dh, dm, tid);
        }
        CP_COMMIT();
        {   // convert P chunk [16][128] -> bf16 hi/mid (overlaps V prefetch)
            int q = tid >> 5, c0 = (tid & 31) * 4;
            float4 v = *(const float4*)&logits[q * LSTRIDE + ch * 128 + c0];
            split_store(pw_hi, pw_mid, q * PSTRIDE + c0 / 2, v);
        }
        CP_WAIT1();
        __syncthreads();
        const uint32_t vbase = ((ch & 1) ? (sb + OFF_K1HI) : (sb + OFF_K0HI));
        const uint32_t vR  = vbase + (uint32_t)((lane & 15) * (KSTRIDE * 4)) + (uint32_t)(dgrp * 16);
        const uint32_t vRm = vR + (uint32_t)(OFF_K0MID - OFF_K0HI);
#pragma unroll
        for (int kk = 0; kk < 4; kk++) {
            int ks = kh * 4 + kk;
            uint32_t ah[4], am[4], bh[2], bm[2];
            LDSM_X4(ah[0], ah[1], ah[2], ah[3], pA + ks * 32);
            LDSM_X4(am[0], am[1], am[2], am[3], pAm + ks * 32);
            LDSM_X2T(bh[0], bh[1], vR + ks * 16 * (KSTRIDE * 4));
            LDSM_X2T(bm[0], bm[1], vRm + ks * 16 * (KSTRIDE * 4));
            mma_bf16(acc, ah, bh);
            mma_bf16(acc, am, bh);
            mma_bf16(acc, ah, bm);
        }
        __syncthreads();
    }

    // cross-half reduction through smem (reuse logits region)
    float* red = logits;
    *(float4*)&red[wid * 128 + lane * 4] = make_float4(acc[0], acc[1], acc[2], acc[3]);
    __syncthreads();
    if (kh == 0) {
        float4 o = *(const float4*)&red[(wid + 1) * 128 + lane * 4];
        acc[0] += o.x; acc[1] += o.y; acc[2] += o.z; acc[3] += o.w;
        int dcol = h * DEPTH + dgrp * 8 + tig * 2;
        *(float2*)&Aout[(size_t)(rb + q0 + gid)     * D_MODEL + dcol] = make_float2(acc[0], acc[1]);
        *(float2*)&Aout[(size_t)(rb + q0 + gid + 8) * D_MODEL + dcol] = make_float2(acc[2], acc[3]);
    }
}

// --------------------- fp32 GEMM (KV projection, exact) --------------------
__global__ __launch_bounds__(256) void gemm_nt_bias(
    const float* __restrict__ A, const float* __restrict__ W,
    const float* __restrict__ bias, float* __restrict__ C,
    int M, int N, int K)
{
    __shared__ float As[16][68];
    __shared__ float Ws[16][68];
    int tid = threadIdx.x;
    int m0 = blockIdx.y * 64, n0 = blockIdx.x * 64;
    int lr = tid >> 2, lq = tid & 3;
    int tx = tid & 15, ty = tid >> 4;
    float acc[4][4];
#pragma unroll
    for (int i = 0; i < 4; i++)
#pragma unroll
        for (int j = 0; j < 4; j++) acc[i][j] = 0.f;
    const float* Aptr = A + (size_t)(m0 + lr) * K + lq * 4;
    const float* Wptr = W + (size_t)(n0 + lr) * K + lq * 4;
    for (int k0 = 0; k0 < K; k0 += 16) {
        float4 av = *(const float4*)(Aptr + k0);
        float4 wv = *(const float4*)(Wptr + k0);
        __syncthreads();
        As[lq*4+0][lr] = av.x; As[lq*4+1][lr] = av.y; As[lq*4+2][lr] = av.z; As[lq*4+3][lr] = av.w;
        Ws[lq*4+0][lr] = wv.x; Ws[lq*4+1][lr] = wv.y; Ws[lq*4+2][lr] = wv.z; Ws[lq*4+3][lr] = wv.w;
        __syncthreads();
#pragma unroll
        for (int kk = 0; kk < 16; kk++) {
            float4 a = *(const float4*)&As[kk][ty * 4];
            float4 w = *(const float4*)&Ws[kk][tx * 4];
            acc[0][0] += a.x*w.x; acc[0][1] += a.x*w.y; acc[0][2] += a.x*w.z; acc[0][3] += a.x*w.w;
            acc[1][0] += a.y*w.x; acc[1][1] += a.y*w.y; acc[1][2] += a.y*w.z; acc[1][3] += a.y*w.w;
            acc[2][0] += a.z*w.x; acc[2][1] += a.z*w.y; acc[2][2] += a.z*w.z; acc[2][3] += a.z*w.w;
            acc[3][0] += a.w*w.x; acc[3][1] += a.w*w.y; acc[3][2] += a.w*w.z; acc[3][3] += a.w*w.w;
        }
    }
    float4 bv = *(const float4*)&bias[n0 + tx * 4];
#pragma unroll
    for (int i = 0; i < 4; i++) {
        float4 o;
        o.x = acc[i][0] + bv.x; o.y = acc[i][1] + bv.y;
        o.z = acc[i][2] + bv.z; o.w = acc[i][3] + bv.w;
        *(float4*)&C[(size_t)(m0 + ty * 4 + i) * N + n0 + tx * 4] = o;
    }
}

// ---------------------------------------------------------------------------
extern "C" void kernel_launch(void* const* d_in, const int* in_sizes, int n_in,
                              void* d_out, int out_size)
{
    const float* Q       = (const float*)d_in[0];
    const float* K       = (const float*)d_in[1];
    // d_in[2] = V (unused: reference derives V from the KV projection)
    const float* WQ_w    = (const float*)d_in[3];
    const float* WQ_b    = (const float*)d_in[4];
    const float* WKV_w   = (const float*)d_in[5];
    const float* WKV_b   = (const float*)d_in[6];
    const float* dense_w = (const float*)d_in[7];
    const float* dense_b = (const float*)d_in[8];

    float* out     = (float*)d_out;
    float* weights = out + (size_t)M_TOTAL * D_MODEL;

    float *qp, *kv, *attn;
    uint32_t *qhp, *qmp, *kvh, *kvm;
    cudaGetSymbolAddress((void**)&qp,   g_Qp);
    cudaGetSymbolAddress((void**)&kv,   g_KV);
    cudaGetSymbolAddress((void**)&attn, g_attn);
    cudaGetSymbolAddress((void**)&qhp,  g_Qh);
    cudaGetSymbolAddress((void**)&qmp,  g_Qm);
    cudaGetSymbolAddress((void**)&kvh,  g_KVh);
    cudaGetSymbolAddress((void**)&kvm,  g_KVm);

    cudaFuncSetAttribute(attn_mma, cudaFuncAttributeMaxDynamicSharedMemorySize, ATTN_SMEM);

    // 1) Qp = Q @ WQ_w^T + b   (tensor core bf16x3)
    gemm_tc<<<dim3(D_MODEL / 128, M_TOTAL / 128), 256>>>(
        Q, WQ_w, WQ_b, qp, M_TOTAL, D_MODEL, D_MODEL);
    // 2) KV = K @ WKV_w^T + b  (exact fp32)
    gemm_nt_bias<<<dim3((2 * DEPTH) / 64, M_TOTAL / 64), 256>>>(
        K, WKV_w, WKV_b, kv, M_TOTAL, 2 * DEPTH, D_MODEL);
    // 3) pre-split Qp (x0.125 folded, exact) and KV to bf16 hi/mid
    split_pre<<<(M_TOTAL * D_MODEL / 4) / 256, 256>>>(
        (const float4*)qp, (uint2*)qhp, (uint2*)qmp, M_TOTAL * D_MODEL / 4, 0.125f);
    split_pre<<<(M_TOTAL * 128 / 4) / 256, 256>>>(
        (const float4*)kv, (uint2*)kvh, (uint2*)kvm, M_TOTAL * 128 / 4, 1.0f);
    // 4) attention
    attn_mma<<<dim3(SEQ / 16, NHEADS, BATCH), 512, ATTN_SMEM>>>(
        qhp, qmp, kvh, kvm, weights, attn);
    // 5) out = attn @ dense_w^T + b  (tensor core bf16x3)
    gemm_tc<<<dim3(D_MODEL / 128, M_TOTAL / 128), 256>>>(
        attn, dense_w, dense_b, out, M_TOTAL, D_MODEL, D_MODEL);
}

// round 11
// speedup vs baseline: 3.2230x; 1.5700x over previous
#include <cuda_runtime.h>
#include <cstdint>
#include <cstddef>

#define D_MODEL 1024
#define NHEADS  16
#define DEPTH   64
#define BATCH   2
#define SEQ     2048
#define M_TOTAL (BATCH * SEQ)

__device__ float g_attn[(size_t)M_TOTAL * D_MODEL];
// pre-split bf16 hi/mid (2 per word), written by GEMM epilogues
__device__ uint32_t g_Qh[(size_t)M_TOTAL * 512];
__device__ uint32_t g_Qm[(size_t)M_TOTAL * 512];
__device__ uint32_t g_KVh[(size_t)M_TOTAL * 64];
__device__ uint32_t g_KVm[(size_t)M_TOTAL * 64];

// ---------------------------------------------------------------------------
// helpers (baseline sm_80-level PTX, legal on compute_103)
// ---------------------------------------------------------------------------
__device__ __forceinline__ uint32_t smem_u32(const void* p) {
    uint32_t a;
    asm("{ .reg .u64 t; cvta.to.shared.u64 t, %1; cvt.u32.u64 %0, t; }" : "=r"(a) : "l"(p));
    return a;
}
__device__ __forceinline__ uint32_t pack_bf16(float lo, float hi) {
    uint32_t r;
    asm("cvt.rn.bf16x2.f32 %0, %1, %2;" : "=r"(r) : "f"(hi), "f"(lo));
    return r;
}
__device__ __forceinline__ float trbf(float x) {
    return __uint_as_float(__float_as_uint(x) & 0xFFFF0000u);
}
__device__ __forceinline__ uint32_t trunc_pack(float a, float b) {
    return __byte_perm(__float_as_uint(a), __float_as_uint(b), 0x7632);
}
__device__ __forceinline__ void mma_bf16(float* c, const uint32_t* a, const uint32_t* b) {
    asm volatile("mma.sync.aligned.m16n8k16.row.col.f32.bf16.bf16.f32 "
        "{%0,%1,%2,%3}, {%4,%5,%6,%7}, {%8,%9}, {%0,%1,%2,%3};"
        : "+f"(c[0]), "+f"(c[1]), "+f"(c[2]), "+f"(c[3])
        : "r"(a[0]), "r"(a[1]), "r"(a[2]), "r"(a[3]), "r"(b[0]), "r"(b[1]));
}
#define LDSM_X2T(r0, r1, addr) \
    asm volatile("ldmatrix.sync.aligned.m8n8.x2.trans.shared.b16 {%0,%1}, [%2];" \
        : "=r"(r0), "=r"(r1) : "r"(addr))
#define CP_ASYNC16(dst, src) \
    asm volatile("cp.async.cg.shared.global [%0], [%1], 16;" :: "r"(dst), "l"(src))
#define CP_COMMIT() asm volatile("cp.async.commit_group;" ::: "memory")
#define CP_WAIT1()  asm volatile("cp.async.wait_group 1;" ::: "memory")
#define CP_WAIT0()  asm volatile("cp.async.wait_group 0;" ::: "memory")

// split one float4 into bf16 hi (truncate) + mid (rn residual), store 2+2 words
__device__ __forceinline__ void split_store(uint32_t* whi, uint32_t* wmid, int wi, float4 v) {
    uint32_t b0 = __float_as_uint(v.x), b1 = __float_as_uint(v.y);
    uint32_t b2 = __float_as_uint(v.z), b3 = __float_as_uint(v.w);
    *(uint2*)(whi + wi) = make_uint2(__byte_perm(b0, b1, 0x7632), __byte_perm(b2, b3, 0x7632));
    float m0 = v.x - __uint_as_float(b0 & 0xFFFF0000u);
    float m1 = v.y - __uint_as_float(b1 & 0xFFFF0000u);
    float m2 = v.z - __uint_as_float(b2 & 0xFFFF0000u);
    float m3 = v.w - __uint_as_float(b3 & 0xFFFF0000u);
    *(uint2*)(wmid + wi) = make_uint2(pack_bf16(m0, m1), pack_bf16(m2, m3));
}

// ===========================================================================
// Tensor-core GEMM bf16x3, 128x128 tile, BK=32. Epilogue writes either fp32 C
// or pre-split bf16 hi/mid arrays (scale folded; exact for powers of two).
// ===========================================================================
#define GSTRIDE 20

__global__ __launch_bounds__(256) void gemm_tc(
    const float* __restrict__ A, const float* __restrict__ W,
    const float* __restrict__ bias, float* __restrict__ C,
    uint32_t* __restrict__ dh, uint32_t* __restrict__ dm, float oscale,
    int M, int N, int K)
{
    __shared__ uint32_t Ahi[128 * GSTRIDE], Amid[128 * GSTRIDE];
    __shared__ uint32_t Bhi[128 * GSTRIDE], Bmid[128 * GSTRIDE];
    const int tid = threadIdx.x, wid = tid >> 5, lane = tid & 31;
    const int gid = lane >> 2, tig = lane & 3;
    const int warp_m = wid & 3, warp_n = wid >> 2;
    const int m0 = blockIdx.y * 128, n0 = blockIdx.x * 128;

    float acc[2][8][4];
#pragma unroll
    for (int mt = 0; mt < 2; mt++)
#pragma unroll
        for (int nt = 0; nt < 8; nt++)
#pragma unroll
            for (int j = 0; j < 4; j++) acc[mt][nt][j] = 0.f;

    for (int k0 = 0; k0 < K; k0 += 32) {
        __syncthreads();
#pragma unroll
        for (int i = 0; i < 4; i++) {
            int e = tid + i * 256;
            int r = e >> 3, w8 = e & 7;
            float4 va = *(const float4*)(A + (size_t)(m0 + r) * K + k0 + w8 * 4);
            split_store(Ahi, Amid, r * GSTRIDE + w8 * 2, va);
            float4 vb = *(const float4*)(W + (size_t)(n0 + r) * K + k0 + w8 * 4);
            split_store(Bhi, Bmid, r * GSTRIDE + w8 * 2, vb);
        }
        __syncthreads();
#pragma unroll
        for (int ds = 0; ds < 2; ds++) {
            uint32_t ah[2][4], am[2][4];
#pragma unroll
            for (int mt = 0; mt < 2; mt++) {
                int r0 = (warp_m * 32 + mt * 16 + gid) * GSTRIDE + ds * 8 + tig;
                int r1 = r0 + 8 * GSTRIDE;
                ah[mt][0] = Ahi[r0];     ah[mt][1] = Ahi[r1];
                ah[mt][2] = Ahi[r0 + 4]; ah[mt][3] = Ahi[r1 + 4];
                am[mt][0] = Amid[r0];     am[mt][1] = Amid[r1];
                am[mt][2] = Amid[r0 + 4]; am[mt][3] = Amid[r1 + 4];
            }
#pragma unroll
            for (int nt = 0; nt < 8; nt++) {
                int wi = (warp_n * 64 + nt * 8 + gid) * GSTRIDE + ds * 8 + tig;
                uint32_t bh[2] = { Bhi[wi], Bhi[wi + 4] };
                uint32_t bm[2] = { Bmid[wi], Bmid[wi + 4] };
#pragma unroll
                for (int mt = 0; mt < 2; mt++) {
                    mma_bf16(acc[mt][nt], ah[mt], bh);
                    mma_bf16(acc[mt][nt], am[mt], bh);
                    mma_bf16(acc[mt][nt], ah[mt], bm);
                }
            }
        }
    }
#pragma unroll
    for (int mt = 0; mt < 2; mt++) {
        int row = m0 + warp_m * 32 + mt * 16 + gid;
#pragma unroll
        for (int nt = 0; nt < 8; nt++) {
            int col = n0 + warp_n * 64 + nt * 8 + tig * 2;
            float2 bv = *(const float2*)&bias[col];
            float v00 = acc[mt][nt][0] + bv.x, v01 = acc[mt][nt][1] + bv.y;
            float v10 = acc[mt][nt][2] + bv.x, v11 = acc[mt][nt][3] + bv.y;
            if (dh) {
                v00 *= oscale; v01 *= oscale; v10 *= oscale; v11 *= oscale;
                size_t w0 = (size_t)row * (N / 2) + col / 2;
                size_t w1 = w0 + (size_t)8 * (N / 2);
                dh[w0] = trunc_pack(v00, v01);
                dm[w0] = pack_bf16(v00 - trbf(v00), v01 - trbf(v01));
                dh[w1] = trunc_pack(v10, v11);
                dm[w1] = pack_bf16(v10 - trbf(v10), v11 - trbf(v11));
            } else {
                *(float2*)&C[(size_t)row * N + col] = make_float2(v00, v01);
                *(float2*)&C[(size_t)(row + 8) * N + col] = make_float2(v10, v11);
            }
        }
    }
}

// --------------- fp32 GEMM for KV (exact), split-output epilogue -----------
__global__ __launch_bounds__(256) void gemm_kv_split(
    const float* __restrict__ A, const float* __restrict__ W,
    const float* __restrict__ bias,
    uint32_t* __restrict__ dh, uint32_t* __restrict__ dm,
    int M, int N, int K)
{
    __shared__ float As[16][68];
    __shared__ float Ws[16][68];
    int tid = threadIdx.x;
    int m0 = blockIdx.y * 64, n0 = blockIdx.x * 64;
    int lr = tid >> 2, lq = tid & 3;
    int tx = tid & 15, ty = tid >> 4;
    float acc[4][4];
#pragma unroll
    for (int i = 0; i < 4; i++)
#pragma unroll
        for (int j = 0; j < 4; j++) acc[i][j] = 0.f;
    const float* Aptr = A + (size_t)(m0 + lr) * K + lq * 4;
    const float* Wptr = W + (size_t)(n0 + lr) * K + lq * 4;
    for (int k0 = 0; k0 < K; k0 += 16) {
        float4 av = *(const float4*)(Aptr + k0);
        float4 wv = *(const float4*)(Wptr + k0);
        __syncthreads();
        As[lq*4+0][lr] = av.x; As[lq*4+1][lr] = av.y; As[lq*4+2][lr] = av.z; As[lq*4+3][lr] = av.w;
        Ws[lq*4+0][lr] = wv.x; Ws[lq*4+1][lr] = wv.y; Ws[lq*4+2][lr] = wv.z; Ws[lq*4+3][lr] = wv.w;
        __syncthreads();
#pragma unroll
        for (int kk = 0; kk < 16; kk++) {
            float4 a = *(const float4*)&As[kk][ty * 4];
            float4 w = *(const float4*)&Ws[kk][tx * 4];
            acc[0][0] += a.x*w.x; acc[0][1] += a.x*w.y; acc[0][2] += a.x*w.z; acc[0][3] += a.x*w.w;
            acc[1][0] += a.y*w.x; acc[1][1] += a.y*w.y; acc[1][2] += a.y*w.z; acc[1][3] += a.y*w.w;
            acc[2][0] += a.z*w.x; acc[2][1] += a.z*w.y; acc[2][2] += a.z*w.z; acc[2][3] += a.z*w.w;
            acc[3][0] += a.w*w.x; acc[3][1] += a.w*w.y; acc[3][2] += a.w*w.z; acc[3][3] += a.w*w.w;
        }
    }
    float4 bv = *(const float4*)&bias[n0 + tx * 4];
#pragma unroll
    for (int i = 0; i < 4; i++) {
        float o0 = acc[i][0] + bv.x, o1 = acc[i][1] + bv.y;
        float o2 = acc[i][2] + bv.z, o3 = acc[i][3] + bv.w;
        size_t w = (size_t)(m0 + ty * 4 + i) * (N / 2) + (n0 + tx * 4) / 2;
        *(uint2*)&dh[w] = make_uint2(trunc_pack(o0, o1), trunc_pack(o2, o3));
        *(uint2*)&dm[w] = make_uint2(pack_bf16(o0 - trbf(o0), o1 - trbf(o1)),
                                     pack_bf16(o2 - trbf(o2), o3 - trbf(o3)));
    }
}

// ---------------------------------------------------------------------------
// Flash attention, TQ=128, 256 threads (8 warps; warp owns 16 q rows).
// Pass A: online (m,s). Pass B: recompute logits -> weights + PV from regs.
// ---------------------------------------------------------------------------
#define KSTR 36                       // words per K/V smem row (144 B)
#define STG  (128 * KSTR * 4)         // 18432 B per stage array
#define OFF_K0HI  0
#define OFF_K0MID (1 * STG)
#define OFF_K1HI  (2 * STG)
#define OFF_K1MID (3 * STG)
#define OFF_V0HI  (4 * STG)
#define OFF_V0MID (5 * STG)
#define OFF_V1HI  (6 * STG)
#define OFF_V1MID (7 * STG)
#define OFF_QHI   (8 * STG)
#define OFF_QMID  (9 * STG)
#define ATTN_SMEM (10 * STG)          // 184320 B

__device__ __forceinline__ void prefetch_kv(
    const uint32_t* __restrict__ KVh, const uint32_t* __restrict__ KVm,
    int rowbase, int voff, uint32_t dhi, uint32_t dmid, int tid)
{
#pragma unroll
    for (int i = 0; i < 8; i++) {
        int e = tid + i * 256;
        int r = e >> 4, t = e & 15, w8 = t & 7;
        const uint32_t* src = ((t & 8) ? KVm : KVh) + (size_t)(rowbase + r) * 64 + voff + w8 * 4;
        uint32_t dst = ((t & 8) ? dmid : dhi) + (uint32_t)(r * 144 + w8 * 16);
        CP_ASYNC16(dst, src);
    }
}

// 16 q rows x 128 keys: c[16][4], bf16x3 (3 MMAs per frag pair)
#define QK_CHUNK(khi, kmid, c) do { \
    _Pragma("unroll") for (int _j = 0; _j < 16; _j++) { \
        (c)[_j][0] = 0.f; (c)[_j][1] = 0.f; (c)[_j][2] = 0.f; (c)[_j][3] = 0.f; } \
    _Pragma("unroll") for (int _ds = 0; _ds < 4; _ds++) { \
        _Pragma("unroll") for (int _j = 0; _j < 16; _j++) { \
            int _wi = (_j * 8 + gid) * KSTR + _ds * 8 + tig; \
            uint32_t _bh[2] = { (khi)[_wi], (khi)[_wi + 4] }; \
            uint32_t _bm[2] = { (kmid)[_wi], (kmid)[_wi + 4] }; \
            mma_bf16((c)[_j], qh[_ds], _bh); \
            mma_bf16((c)[_j], qm[_ds], _bh); \
            mma_bf16((c)[_j], qh[_ds], _bm); \
        } } } while (0)

__global__ __launch_bounds__(256, 1) void attn_flash(
    const uint32_t* __restrict__ Qh, const uint32_t* __restrict__ Qm,
    const uint32_t* __restrict__ KVh, const uint32_t* __restrict__ KVm,
    float* __restrict__ Wout, float* __restrict__ Aout)
{
    extern __shared__ char sm[];
    const int tid = threadIdx.x, wid = tid >> 5, lane = tid & 31;
    const int gid = lane >> 2, tig = lane & 3;
    const int b = blockIdx.z, h = blockIdx.y, q0 = blockIdx.x * 128;
    const uint32_t sb = smem_u32(sm);
    const int rb = b * SEQ;

    uint32_t* qw_hi  = (uint32_t*)(sm + OFF_QHI);
    uint32_t* qw_mid = (uint32_t*)(sm + OFF_QMID);

    prefetch_kv(KVh, KVm, rb, 0, sb + OFF_K0HI, sb + OFF_K0MID, tid);
    CP_COMMIT();

    // stage Q rows q0..q0+127 (32 words hi + 32 mid per row)
#pragma unroll
    for (int i = 0; i < 4; i++) {
        int e = tid + i * 256;
        int r = e >> 3, cw = (e & 7) * 4;
        size_t g = (size_t)(rb + q0 + r) * 512 + h * 32 + cw;
        *(uint4*)&qw_hi[r * KSTR + cw]  = *(const uint4*)&Qh[g];
        *(uint4*)&qw_mid[r * KSTR + cw] = *(const uint4*)&Qm[g];
    }
    __syncthreads();

    uint32_t qh[4][4], qm[4][4];
#pragma unroll
    for (int ds = 0; ds < 4; ds++) {
        int w0 = (wid * 16 + gid) * KSTR + ds * 8 + tig, w1 = w0 + 8 * KSTR;
        qh[ds][0] = qw_hi[w0];  qh[ds][1] = qw_hi[w1];
        qh[ds][2] = qw_hi[w0 + 4]; qh[ds][3] = qw_hi[w1 + 4];
        qm[ds][0] = qw_mid[w0]; qm[ds][1] = qw_mid[w1];
        qm[ds][2] = qw_mid[w0 + 4]; qm[ds][3] = qw_mid[w1 + 4];
    }

    float m0 = -1e30f, s0 = 0.f, m1 = -1e30f, s1 = 0.f;
    float c[16][4];

    // ---- Pass A: online row max & expsum ----
    for (int ch = 0; ch < 16; ch++) {
        if (ch < 15) {
            int alt = (ch + 1) & 1;
            prefetch_kv(KVh, KVm, rb + (ch + 1) * 128, 0,
                        sb + (alt ? OFF_K1HI : OFF_K0HI),
                        sb + (alt ? OFF_K1MID : OFF_K0MID), tid);
        }
        CP_COMMIT(); CP_WAIT1(); __syncthreads();
        const uint32_t* khi  = (const uint32_t*)(sm + ((ch & 1) ? OFF_K1HI : OFF_K0HI));
        const uint32_t* kmid = (const uint32_t*)(sm + ((ch & 1) ? OFF_K1MID : OFF_K0MID));
        QK_CHUNK(khi, kmid, c);
        float mx0 = -1e30f, mx1 = -1e30f;
#pragma unroll
        for (int j = 0; j < 16; j++) {
            mx0 = fmaxf(mx0, fmaxf(c[j][0], c[j][1]));
            mx1 = fmaxf(mx1, fmaxf(c[j][2], c[j][3]));
        }
        mx0 = fmaxf(mx0, __shfl_xor_sync(0xffffffffu, mx0, 1));
        mx0 = fmaxf(mx0, __shfl_xor_sync(0xffffffffu, mx0, 2));
        mx1 = fmaxf(mx1, __shfl_xor_sync(0xffffffffu, mx1, 1));
        mx1 = fmaxf(mx1, __shfl_xor_sync(0xffffffffu, mx1, 2));
        float nm0 = fmaxf(m0, mx0), nm1 = fmaxf(m1, mx1);
        float a0 = 0.f, a1 = 0.f;
#pragma unroll
        for (int j = 0; j < 16; j++) {
            a0 += __expf(c[j][0] - nm0) + __expf(c[j][1] - nm0);
            a1 += __expf(c[j][2] - nm1) + __expf(c[j][3] - nm1);
        }
        a0 += __shfl_xor_sync(0xffffffffu, a0, 1);
        a0 += __shfl_xor_sync(0xffffffffu, a0, 2);
        a1 += __shfl_xor_sync(0xffffffffu, a1, 1);
        a1 += __shfl_xor_sync(0xffffffffu, a1, 2);
        s0 = s0 * __expf(m0 - nm0) + a0; m0 = nm0;
        s1 = s1 * __expf(m1 - nm1) + a1; m1 = nm1;
        __syncthreads();
    }
    CP_WAIT0();
    const float inv0 = 1.f / s0, inv1 = 1.f / s1;
    __syncthreads();

    // ---- Pass B: weights + PV ----
    prefetch_kv(KVh, KVm, rb, 0,  sb + OFF_K0HI, sb + OFF_K0MID, tid);
    prefetch_kv(KVh, KVm, rb, 32, sb + OFF_V0HI, sb + OFF_V0MID, tid);
    CP_COMMIT();

    float pv[8][4];
#pragma unroll
    for (int n = 0; n < 8; n++) { pv[n][0] = pv[n][1] = pv[n][2] = pv[n][3] = 0.f; }

    float* wrow0 = Wout + ((size_t)(b * NHEADS + h) * SEQ + (q0 + wid * 16 + gid)) * SEQ;
    float* wrow1 = wrow0 + (size_t)8 * SEQ;

    for (int ch = 0; ch < 16; ch++) {
        if (ch < 15) {
            int alt = (ch + 1) & 1;
            prefetch_kv(KVh, KVm, rb + (ch + 1) * 128, 0,
                        sb + (alt ? OFF_K1HI : OFF_K0HI),
                        sb + (alt ? OFF_K1MID : OFF_K0MID), tid);
            prefetch_kv(KVh, KVm, rb + (ch + 1) * 128, 32,
                        sb + (alt ? OFF_V1HI : OFF_V0HI),
                        sb + (alt ? OFF_V1MID : OFF_V0MID), tid);
        }
        CP_COMMIT(); CP_WAIT1(); __syncthreads();
        int cur = ch & 1;
        const uint32_t* khi  = (const uint32_t*)(sm + (cur ? OFF_K1HI : OFF_K0HI));
        const uint32_t* kmid = (const uint32_t*)(sm + (cur ? OFF_K1MID : OFF_K0MID));
        const uint32_t vbhi  = sb + (cur ? OFF_V1HI : OFF_V0HI);
        const uint32_t vbmid = sb + (cur ? OFF_V1MID : OFF_V0MID);

        QK_CHUNK(khi, kmid, c);

#pragma unroll
        for (int j = 0; j < 16; j++) {
            float p0 = __expf(c[j][0] - m0) * inv0;
            float p1 = __expf(c[j][1] - m0) * inv0;
            float p2 = __expf(c[j][2] - m1) * inv1;
            float p3 = __expf(c[j][3] - m1) * inv1;
            *(float2*)&wrow0[ch * 128 + j * 8 + tig * 2] = make_float2(p0, p1);
            *(float2*)&wrow1[ch * 128 + j * 8 + tig * 2] = make_float2(p2, p3);
            c[j][0] = p0; c[j][1] = p1; c[j][2] = p2; c[j][3] = p3;
        }

#pragma unroll
        for (int s = 0; s < 8; s++) {
            uint32_t ah[4], am[4];
            float e00 = c[2*s][0],   e01 = c[2*s][1],   e02 = c[2*s][2],   e03 = c[2*s][3];
            float e10 = c[2*s+1][0], e11 = c[2*s+1][1], e12 = c[2*s+1][2], e13 = c[2*s+1][3];
            ah[0] = trunc_pack(e00, e01); ah[1] = trunc_pack(e02, e03);
            ah[2] = trunc_pack(e10, e11); ah[3] = trunc_pack(e12, e13);
            am[0] = pack_bf16(e00 - trbf(e00), e01 - trbf(e01));
            am[1] = pack_bf16(e02 - trbf(e02), e03 - trbf(e03));
            am[2] = pack_bf16(e10 - trbf(e10), e11 - trbf(e11));
            am[3] = pack_bf16(e12 - trbf(e12), e13 - trbf(e13));
            uint32_t vrow = (uint32_t)((s * 16 + (lane & 15)) * 144);
#pragma unroll
            for (int n = 0; n < 8; n++) {
                uint32_t bh[2], bm[2];
                LDSM_X2T(bh[0], bh[1], vbhi + vrow + n * 16);
                LDSM_X2T(bm[0], bm[1], vbmid + vrow + n * 16);
                mma_bf16(pv[n], ah, bh);
                mma_bf16(pv[n], am, bh);
                mma_bf16(pv[n], ah, bm);
            }
        }
        __syncthreads();
    }

    int row0 = rb + q0 + wid * 16 + gid;
#pragma unroll
    for (int n = 0; n < 8; n++) {
        int dcol = h * DEPTH + n * 8 + tig * 2;
        *(float2*)&Aout[(size_t)row0 * D_MODEL + dcol]       = make_float2(pv[n][0], pv[n][1]);
        *(float2*)&Aout[(size_t)(row0 + 8) * D_MODEL + dcol] = make_float2(pv[n][2], pv[n][3]);
    }
}

// ---------------------------------------------------------------------------
extern "C" void kernel_launch(void* const* d_in, const int* in_sizes, int n_in,
                              void* d_out, int out_size)
{
    const float* Q       = (const float*)d_in[0];
    const float* K       = (const float*)d_in[1];
    // d_in[2] = V (unused: reference derives V from the KV projection)
    const float* WQ_w    = (const float*)d_in[3];
    const float* WQ_b    = (const float*)d_in[4];
    const float* WKV_w   = (const float*)d_in[5];
    const float* WKV_b   = (const float*)d_in[6];
    const float* dense_w = (const float*)d_in[7];
    const float* dense_b = (const float*)d_in[8];

    float* out     = (float*)d_out;
    float* weights = out + (size_t)M_TOTAL * D_MODEL;

    float* attn;
    uint32_t *qhp, *qmp, *kvh, *kvm;
    cudaGetSymbolAddress((void**)&attn, g_attn);
    cudaGetSymbolAddress((void**)&qhp,  g_Qh);
    cudaGetSymbolAddress((void**)&qmp,  g_Qm);
    cudaGetSymbolAddress((void**)&kvh,  g_KVh);
    cudaGetSymbolAddress((void**)&kvm,  g_KVm);

    cudaFuncSetAttribute(attn_flash, cudaFuncAttributeMaxDynamicSharedMemorySize, ATTN_SMEM);

    // 1) Qp-split = 0.125*(Q @ WQ_w^T + b)  -> g_Qh/g_Qm  (no fp32 Qp at all)
    gemm_tc<<<dim3(D_MODEL / 128, M_TOTAL / 128), 256>>>(
        Q, WQ_w, WQ_b, nullptr, qhp, qmp, 0.125f, M_TOTAL, D_MODEL, D_MODEL);
    // 2) KV-split = K @ WKV_w^T + b  (exact fp32 compute) -> g_KVh/g_KVm
    gemm_kv_split<<<dim3((2 * DEPTH) / 64, M_TOTAL / 64), 256>>>(
        K, WKV_w, WKV_b, kvh, kvm, M_TOTAL, 2 * DEPTH, D_MODEL);
    // 3) flash attention: weights + context
    attn_flash<<<dim3(SEQ / 128, NHEADS, BATCH), 256, ATTN_SMEM>>>(
        qhp, qmp, kvh, kvm, weights, attn);
    // 4) out = attn @ dense_w^T + b (fp32 output)
    gemm_tc<<<dim3(D_MODEL / 128, M_TOTAL / 128), 256>>>(
        attn, dense_w, dense_b, out, nullptr, nullptr, 1.f, M_TOTAL, D_MODEL, D_MODEL);
}